// round 12
// baseline (speedup 1.0000x reference)
#include <cuda_runtime.h>
#include <cuda_fp16.h>
#include <cstdint>

#define O_N   50000
#define T_N   200000
#define DIN   128
#define HID   512
#define DOUT  128

// padded row counts (one extra M-tile so GEMM loaders need no bounds checks)
#define T_PAD 200064
#define O_PAD 50048

// ---------------- device scratch (allocation-free rule) -----------------------
__device__ __half  g_objh [(size_t)O_N * DIN];    // obj fp16 (indexed, no pad needed)
__device__ __half  g_predh[(size_t)T_PAD * DIN];  // pred fp16 (padded)
__device__ __half  g_h    [(size_t)T_PAD * 512];  // [T, 512] fp16 (padded)
__device__ float   g_pool [(size_t)O_N * HID];    // fp32 accum
__device__ __half  g_pool16[(size_t)O_PAD * 512]; // pooled fp16 (padded)
__device__ __half  g_h2   [(size_t)O_PAD * 512];  // [O, 512] fp16 (padded)
__device__ float   g_cnt  [O_N];
__device__ __half  g_bt1[(size_t)512  * 384];     // [N,K] fp16 (W1a^T)
__device__ __half  g_bt2[(size_t)1152 * 512];     // [N,K] fp16 (W1b^T)
__device__ __half  g_bt3[(size_t)512  * 512];     // [N,K] fp16 (W2a^T)
__device__ __half  g_bt4[(size_t)128  * 512];     // [N,K] fp16 (W2b^T)

// ---------------- PTX helpers -------------------------------------------------
__device__ __forceinline__ uint32_t smem_u32(const void* p) {
    uint32_t a;
    asm("{ .reg .u64 t; cvta.to.shared.u64 t, %1; cvt.u32.u64 %0, t; }" : "=r"(a) : "l"(p));
    return a;
}
__device__ __forceinline__ void cp_async16(uint32_t dst, const void* src) {
    asm volatile("cp.async.cg.shared.global [%0], [%1], 16;"
                 :: "r"(dst), "l"(src));
}
__device__ __forceinline__ void ldm_x4(uint32_t& r0, uint32_t& r1, uint32_t& r2,
                                       uint32_t& r3, uint32_t addr) {
    asm volatile("ldmatrix.sync.aligned.m8n8.x4.shared.b16 {%0,%1,%2,%3}, [%4];"
                 : "=r"(r0), "=r"(r1), "=r"(r2), "=r"(r3) : "r"(addr));
}
__device__ __forceinline__ void mma_f16(float* c, const uint32_t* a, const uint32_t* b) {
    asm volatile("mma.sync.aligned.m16n8k16.row.col.f32.f16.f16.f32 "
                 "{%0,%1,%2,%3}, {%4,%5,%6,%7}, {%8,%9}, {%0,%1,%2,%3};"
                 : "+f"(c[0]), "+f"(c[1]), "+f"(c[2]), "+f"(c[3])
                 : "r"(a[0]), "r"(a[1]), "r"(a[2]), "r"(a[3]), "r"(b[0]), "r"(b[1]));
}
__device__ __forceinline__ void red_add2(float* p, float a, float b) {
    asm volatile("red.global.add.v2.f32 [%0], {%1,%2};"
                 :: "l"(p), "f"(a), "f"(b) : "memory");
}

// ---------------- prep 1: zero pooled/cnt + obj/pred fp32->fp16 ----------------
__global__ void prep1(const float4* __restrict__ obj, __half2* __restrict__ objh,
                      const float4* __restrict__ pred, __half2* __restrict__ predh,
                      float4* __restrict__ pool4, float* __restrict__ cnt) {
    int i = blockIdx.x * 256 + threadIdx.x;
    const int n4_obj  = O_N * DIN / 4;
    const int n4_pred = T_N * DIN / 4;
    const int n4_pool = O_N * HID / 4;
    if (i < n4_pool) pool4[i] = make_float4(0.f, 0.f, 0.f, 0.f);
    if (i < O_N) cnt[i] = 0.f;
    if (i < n4_obj) {
        float4 v = obj[i];
        objh[2*i]   = __halves2half2(__float2half_rn(v.x), __float2half_rn(v.y));
        objh[2*i+1] = __halves2half2(__float2half_rn(v.z), __float2half_rn(v.w));
    }
    if (i < n4_pred) {
        float4 v = pred[i];
        predh[2*i]   = __halves2half2(__float2half_rn(v.x), __float2half_rn(v.y));
        predh[2*i+1] = __halves2half2(__float2half_rn(v.z), __float2half_rn(v.w));
    }
}

// ---------------- prep 2: all weight transposes + degree counts ----------------
__global__ void prep2(const float* __restrict__ W1a, const float* __restrict__ W1b,
                      const float* __restrict__ W2a, const float* __restrict__ W2b,
                      __half* __restrict__ bt1, __half* __restrict__ bt2,
                      __half* __restrict__ bt3, __half* __restrict__ bt4,
                      const int* __restrict__ edges, float* __restrict__ cnt) {
    int i = blockIdx.x * 256 + threadIdx.x;
    if (i < T_N) {
        atomicAdd(&cnt[edges[2*i]], 1.0f);
        atomicAdd(&cnt[edges[2*i + 1]], 1.0f);
    }
    const float* W; __half* Bt; int K, N, idx;
    if (i < 196608)       { W = W1a; Bt = bt1; K = 384; N = 512;  idx = i; }
    else if (i < 786432)  { W = W1b; Bt = bt2; K = 512; N = 1152; idx = i - 196608; }
    else if (i < 1048576) { W = W2a; Bt = bt3; K = 512; N = 512;  idx = i - 786432; }
    else if (i < 1114112) { W = W2b; Bt = bt4; K = 512; N = 128;  idx = i - 1048576; }
    else return;
    int n = idx / K, k = idx - n * K;
    Bt[idx] = __float2half_rn(W[(size_t)k * N + n]);
}

// pooled/counts -> plain fp16
__global__ void pscale_conv(const float4* __restrict__ pooled, const float* __restrict__ cnt,
                            __half* __restrict__ p16) {
    int i = blockIdx.x * 256 + threadIdx.x;
    if (i >= O_N * (HID / 4)) return;
    int r = i >> 7;
    float c = fminf(fmaxf(cnt[r], 1.0f), 50000.0f);
    float s = 1.0f / c;
    float4 v = pooled[i];
    __half* row = p16 + (size_t)r * 512;
    int c0 = (i & 127) * 4;
    *(__half2*)(row + c0)     = __halves2half2(__float2half_rn(v.x * s), __float2half_rn(v.y * s));
    *(__half2*)(row + c0 + 2) = __halves2half2(__float2half_rn(v.z * s), __float2half_rn(v.w * s));
}

// ---------------- shared GEMM machinery ---------------------------------------
// CTA 128x128, 4 warps (64x64), BK=64, 2-stage pipeline, 128B-row swizzle.
// Next chunk's cp.asyncs are interleaved into the ks loop (4 per step).
#define BM 128
#define BN 128
#define BK 64
#define STG 2
#define STG_BYTES 32768

struct AddrCtx {
    uint32_t rbA[4], rbB[4], xoff[4];
};
__device__ __forceinline__ void make_ctx(AddrCtx& cx, int wm, int wn, int lane) {
    #pragma unroll
    for (int mf = 0; mf < 4; mf++) cx.rbA[mf] = (uint32_t)((wm + mf * 16 + (lane & 15)) * 128);
    #pragma unroll
    for (int bi = 0; bi < 4; bi++) cx.rbB[bi] = (uint32_t)((wn + bi * 16 + (lane & 15)) * 128);
    #pragma unroll
    for (int ks = 0; ks < 4; ks++)
        cx.xoff[ks] = (uint32_t)((((ks * 2 + (lane >> 4)) ^ (lane & 7))) << 4);
}

// one chunk of compute with a per-ks load callback (issues next chunk's loads)
template<class LoadFn>
__device__ __forceinline__ void compute_chunk_il(uint32_t sa, uint32_t sb,
                                                 const AddrCtx& cx,
                                                 float acc[4][8][4], LoadFn&& ld) {
    #pragma unroll
    for (int ks = 0; ks < 4; ks++) {
        ld(ks);
        const uint32_t sax = sa + cx.xoff[ks];
        const uint32_t sbx = sb + cx.xoff[ks];
        uint32_t a[4][4], b[8][2];
        #pragma unroll
        for (int mf = 0; mf < 4; mf++)
            ldm_x4(a[mf][0], a[mf][1], a[mf][2], a[mf][3], sax + cx.rbA[mf]);
        #pragma unroll
        for (int bi = 0; bi < 4; bi++) {
            uint32_t r0, r1, r2, r3;
            ldm_x4(r0, r1, r2, r3, sbx + cx.rbB[bi]);
            b[bi*2+0][0] = r0; b[bi*2+0][1] = r2;
            b[bi*2+1][0] = r1; b[bi*2+1][1] = r3;
        }
        #pragma unroll
        for (int mf = 0; mf < 4; mf++)
            #pragma unroll
            for (int nf = 0; nf < 8; nf++)
                mma_f16(acc[mf][nf], a[mf], b[nf]);
    }
}

// ---------------- GEMM1 with fused edge gather --------------------------------
__global__ void __launch_bounds__(128, 3)
g1_gemm(const __half* __restrict__ objh, const __half* __restrict__ predh,
        const int* __restrict__ edges, const __half* __restrict__ Bt,
        const float* __restrict__ bias, __half* __restrict__ outh)
{
    extern __shared__ char smem[];
    const int tid  = threadIdx.x;
    const int wid  = tid >> 5;
    const int lane = tid & 31;
    const int m0   = blockIdx.y * BM;
    const int n0   = blockIdx.x * BN;
    const int wm   = (wid >> 1) * 64;
    const int wn   = (wid & 1) * 64;
    const int M    = T_N;
    const int Kc   = 384;
    const uint32_t sbase = smem_u32(smem);

    int2* esm = (int2*)(smem + STG * STG_BYTES);
    {
        int gr = m0 + tid;
        esm[tid] = (gr < M) ? *(const int2*)&edges[2*gr] : make_int2(0, 0);
    }
    __syncthreads();

    AddrCtx cx; make_ctx(cx, wm, wn, lane);
    const int lrow = tid >> 3, lch = tid & 7;
    const uint32_t off0 = (uint32_t)(lrow * 128 + ((lch ^ (lrow & 7)) << 4));
    const __half* bBase = Bt + (size_t)(n0 + lrow) * Kc + lch * 8;

    float acc[4][8][4];
    #pragma unroll
    for (int i = 0; i < 4; i++)
        #pragma unroll
        for (int j = 0; j < 8; j++)
            #pragma unroll
            for (int k = 0; k < 4; k++) acc[i][j][k] = 0.f;

    // A-source resolver for row index r (0..127) at chunk `it`
    auto a_src = [&](int it, int row) -> const __half* {
        const int kp  = it * BK;
        const int reg = kp >> 7;
        const int kc  = (kp & 127) + lch * 8;
        if (reg == 0)      return objh  + (size_t)esm[row].x * DIN + kc;
        else if (reg == 1) return predh + (size_t)(m0 + row) * DIN + kc;
        else               return objh  + (size_t)esm[row].y * DIN + kc;
    };
    auto ld_full = [&](int it, int buf) {
        uint32_t sa = sbase + buf * STG_BYTES;
        uint32_t sb = sa + 16384;
        #pragma unroll
        for (int t = 0; t < 8; t++)
            cp_async16(sa + off0 + t * 2048, a_src(it, lrow + t * 16));
        const __half* pb = bBase + it * BK;
        #pragma unroll
        for (int t = 0; t < 8; t++) {
            cp_async16(sb + off0 + t * 2048, pb);
            pb += 16 * Kc;
        }
    };

    const int NC = Kc / BK;   // 6
    ld_full(0, 0);
    asm volatile("cp.async.commit_group;" ::: "memory");
    for (int it = 0; it < NC; it++) {
        asm volatile("cp.async.wait_group 0;" ::: "memory");
        __syncthreads();
        const int nxt = it + 1;
        uint32_t sa  = sbase + (it  & 1) * STG_BYTES;
        uint32_t sa2 = sbase + (nxt & 1) * STG_BYTES;
        uint32_t sb2 = sa2 + 16384;
        compute_chunk_il(sa, sa + 16384, cx, acc, [&](int ks) {
            if (nxt < NC) {
                int t0 = 2 * ks, t1 = 2 * ks + 1;
                cp_async16(sa2 + off0 + t0 * 2048, a_src(nxt, lrow + t0 * 16));
                cp_async16(sa2 + off0 + t1 * 2048, a_src(nxt, lrow + t1 * 16));
                const __half* pb = bBase + nxt * BK + (size_t)t0 * 16 * Kc;
                cp_async16(sb2 + off0 + t0 * 2048, pb);
                cp_async16(sb2 + off0 + t1 * 2048, pb + 16 * Kc);
            }
        });
        asm volatile("cp.async.commit_group;" ::: "memory");
    }

    float bc[8][2];
    #pragma unroll
    for (int nf = 0; nf < 8; nf++) {
        float2 bv = __ldg((const float2*)&bias[n0 + wn + nf * 8 + (lane & 3) * 2]);
        bc[nf][0] = bv.x; bc[nf][1] = bv.y;
    }
    #pragma unroll
    for (int mf = 0; mf < 4; mf++)
        #pragma unroll
        for (int rh = 0; rh < 2; rh++) {
            const int gr = m0 + wm + mf * 16 + (lane >> 2) + rh * 8;
            if (gr >= M) continue;
            #pragma unroll
            for (int nf = 0; nf < 8; nf++) {
                const int col = n0 + wn + nf * 8 + (lane & 3) * 2;
                float v0 = fmaxf(acc[mf][nf][rh*2+0] + bc[nf][0], 0.f);
                float v1 = fmaxf(acc[mf][nf][rh*2+1] + bc[nf][1], 0.f);
                *(__half2*)&outh[(size_t)gr * HID + col] =
                    __halves2half2(__float2half_rn(v0), __float2half_rn(v1));
            }
        }
}

// ---------------- generic GEMM -------------------------------------------------
// A padded beyond M (garbage rows discarded by guarded epilogue).
// EPI 0: fp32 store    EPI 2: GEMM2 router    EPI 3: plain fp16 store
template<int EPI>
__global__ void __launch_bounds__(128, 3)
mma_gemm(const __half* __restrict__ A, const __half* __restrict__ Bt,
         const float* __restrict__ bias, float* __restrict__ outf,
         __half* __restrict__ outh,
         int M, int strideA, int Kc, int ostride,
         const int* __restrict__ edges, float* __restrict__ pooled,
         float* __restrict__ newp)
{
    extern __shared__ char smem[];
    const int tid  = threadIdx.x;
    const int wid  = tid >> 5;
    const int lane = tid & 31;
    const int m0   = blockIdx.y * BM;
    const int n0   = blockIdx.x * BN;
    const int wm   = (wid >> 1) * 64;
    const int wn   = (wid & 1) * 64;
    const uint32_t sbase = smem_u32(smem);

    AddrCtx cx; make_ctx(cx, wm, wn, lane);
    const int lrow = tid >> 3, lch = tid & 7;
    const uint32_t off0 = (uint32_t)(lrow * 128 + ((lch ^ (lrow & 7)) << 4));
    const __half* aBase = A  + (size_t)(m0 + lrow) * strideA + lch * 8;
    const __half* bBase = Bt + (size_t)(n0 + lrow) * Kc      + lch * 8;

    float acc[4][8][4];
    #pragma unroll
    for (int i = 0; i < 4; i++)
        #pragma unroll
        for (int j = 0; j < 8; j++)
            #pragma unroll
            for (int k = 0; k < 4; k++) acc[i][j][k] = 0.f;

    auto ld_full = [&](int it, int buf) {
        uint32_t sa = sbase + buf * STG_BYTES;
        uint32_t sb = sa + 16384;
        const __half* pa = aBase + it * BK;
        const __half* pb = bBase + it * BK;
        #pragma unroll
        for (int t = 0; t < 8; t++) {
            cp_async16(sa + off0 + t * 2048, pa);
            pa += 16 * strideA;
        }
        #pragma unroll
        for (int t = 0; t < 8; t++) {
            cp_async16(sb + off0 + t * 2048, pb);
            pb += 16 * Kc;
        }
    };

    const int NC = Kc / BK;
    ld_full(0, 0);
    asm volatile("cp.async.commit_group;" ::: "memory");
    for (int it = 0; it < NC; it++) {
        asm volatile("cp.async.wait_group 0;" ::: "memory");
        __syncthreads();
        const int nxt = it + 1;
        uint32_t sa  = sbase + (it  & 1) * STG_BYTES;
        uint32_t sa2 = sbase + (nxt & 1) * STG_BYTES;
        uint32_t sb2 = sa2 + 16384;
        compute_chunk_il(sa, sa + 16384, cx, acc, [&](int ks) {
            if (nxt < NC) {
                int t0 = 2 * ks, t1 = 2 * ks + 1;
                const __half* pa = aBase + nxt * BK + (size_t)t0 * 16 * strideA;
                const __half* pb = bBase + nxt * BK + (size_t)t0 * 16 * Kc;
                cp_async16(sa2 + off0 + t0 * 2048, pa);
                cp_async16(sa2 + off0 + t1 * 2048, pa + 16 * strideA);
                cp_async16(sb2 + off0 + t0 * 2048, pb);
                cp_async16(sb2 + off0 + t1 * 2048, pb + 16 * Kc);
            }
        });
        asm volatile("cp.async.commit_group;" ::: "memory");
    }

    float bc[8][2];
    #pragma unroll
    for (int nf = 0; nf < 8; nf++) {
        float2 bv = __ldg((const float2*)&bias[n0 + wn + nf * 8 + (lane & 3) * 2]);
        bc[nf][0] = bv.x; bc[nf][1] = bv.y;
    }

    #pragma unroll
    for (int mf = 0; mf < 4; mf++)
        #pragma unroll
        for (int rh = 0; rh < 2; rh++) {
            const int gr = m0 + wm + mf * 16 + (lane >> 2) + rh * 8;
            if (gr >= M) continue;
            int es = 0, eo = 0;
            if (EPI == 2) { es = edges[2*gr]; eo = edges[2*gr + 1]; }
            #pragma unroll
            for (int nf = 0; nf < 8; nf++) {
                const int col = n0 + wn + nf * 8 + (lane & 3) * 2;
                float v0 = fmaxf(acc[mf][nf][rh*2+0] + bc[nf][0], 0.f);
                float v1 = fmaxf(acc[mf][nf][rh*2+1] + bc[nf][1], 0.f);
                if (EPI == 0) {
                    *(float2*)&outf[(size_t)gr * ostride + col] = make_float2(v0, v1);
                } else if (EPI == 3) {
                    *(__half2*)&outh[(size_t)gr * ostride + col] =
                        __halves2half2(__float2half_rn(v0), __float2half_rn(v1));
                } else {
                    if (col < HID) {
                        red_add2(&pooled[(size_t)es * HID + col], v0, v1);
                    } else if (col < HID + DOUT) {
                        *(float2*)&newp[(size_t)gr * DOUT + (col - HID)] = make_float2(v0, v1);
                    } else {
                        red_add2(&pooled[(size_t)eo * HID + (col - HID - DOUT)], v0, v1);
                    }
                }
            }
        }
}

// ---------------- launch ------------------------------------------------------
// 7 launches; GEMM2 is launch #4 (the profiled slot).
extern "C" void kernel_launch(void* const* d_in, const int* in_sizes, int n_in,
                              void* d_out, int out_size) {
    const float* obj  = (const float*)d_in[0];
    const float* pred = (const float*)d_in[1];
    const int*   edges= (const int*)  d_in[2];
    const float* W1a  = (const float*)d_in[3];
    const float* b1a  = (const float*)d_in[4];
    const float* W1b  = (const float*)d_in[5];
    const float* b1b  = (const float*)d_in[6];
    const float* W2a  = (const float*)d_in[7];
    const float* b2a  = (const float*)d_in[8];
    const float* W2b  = (const float*)d_in[9];
    const float* b2b  = (const float*)d_in[10];

    float* out     = (float*)d_out;
    float* new_obj = out;                       // [O, 128]
    float* new_p   = out + (size_t)O_N * DOUT;  // [T, 128]

    __half *objh, *predh, *h16, *p16, *h2, *bt1, *bt2, *bt3, *bt4;
    float *pooled, *cnt;
    cudaGetSymbolAddress((void**)&objh,   g_objh);
    cudaGetSymbolAddress((void**)&predh,  g_predh);
    cudaGetSymbolAddress((void**)&h16,    g_h);
    cudaGetSymbolAddress((void**)&pooled, g_pool);
    cudaGetSymbolAddress((void**)&p16,    g_pool16);
    cudaGetSymbolAddress((void**)&h2,     g_h2);
    cudaGetSymbolAddress((void**)&cnt,    g_cnt);
    cudaGetSymbolAddress((void**)&bt1,    g_bt1);
    cudaGetSymbolAddress((void**)&bt2,    g_bt2);
    cudaGetSymbolAddress((void**)&bt3,    g_bt3);
    cudaGetSymbolAddress((void**)&bt4,    g_bt4);

    const int SMEM_G  = STG * STG_BYTES;          // 65536
    const int SMEM_G1 = SMEM_G + 128 * 8;         // + edge cache (1 KB)
    cudaFuncSetAttribute((const void*)g1_gemm,     cudaFuncAttributeMaxDynamicSharedMemorySize, SMEM_G1);
    cudaFuncSetAttribute((const void*)mma_gemm<0>, cudaFuncAttributeMaxDynamicSharedMemorySize, SMEM_G);
    cudaFuncSetAttribute((const void*)mma_gemm<2>, cudaFuncAttributeMaxDynamicSharedMemorySize, SMEM_G);
    cudaFuncSetAttribute((const void*)mma_gemm<3>, cudaFuncAttributeMaxDynamicSharedMemorySize, SMEM_G);

    const int MT_T = (T_N + 127) / 128;   // 1563
    const int MT_O = (O_N + 127) / 128;   // 391

    // 1: zero pooled/cnt + obj/pred fp16 converts
    {   int span = T_N * DIN / 4;   // 6.4M
        prep1<<<(span + 255) / 256, 256>>>(
            (const float4*)obj, (__half2*)objh,
            (const float4*)pred, (__half2*)predh,
            (float4*)pooled, cnt); }

    // 2: all weight transposes + degree counts
    prep2<<<(1114112 + 255) / 256, 256>>>(W1a, W1b, W2a, W2b,
                                          bt1, bt2, bt3, bt4, edges, cnt);

    // 3: GEMM1 (fused gather)
    g1_gemm<<<dim3(4, MT_T), 128, SMEM_G1>>>(objh, predh, edges, bt1, b1a, h16);

    // 4: GEMM2 (scatter s/o + new_p)   <-- profiled slot
    mma_gemm<2><<<dim3(9, MT_T), 128, SMEM_G>>>(
        h16, bt2, b1b, nullptr, nullptr,
        T_N, 512, 512, 0, edges, pooled, new_p);

    // 5: pooled scale + fp16
    pscale_conv<<<(O_N * (HID / 4) + 255) / 256, 256>>>((const float4*)pooled, cnt, p16);

    // 6: GEMM3
    mma_gemm<3><<<dim3(4, MT_O), 128, SMEM_G>>>(
        p16, bt3, b2a, nullptr, h2,
        O_N, 512, 512, HID, nullptr, nullptr, nullptr);

    // 7: GEMM4
    mma_gemm<0><<<dim3(1, MT_O), 128, SMEM_G>>>(
        h2, bt4, b2b, new_obj, nullptr,
        O_N, 512, 512, DOUT, nullptr, nullptr, nullptr);
}

// round 13
// speedup vs baseline: 1.0489x; 1.0489x over previous
#include <cuda_runtime.h>
#include <cuda_fp16.h>
#include <cstdint>

#define O_N   50000
#define T_N   200000
#define DIN   128
#define HID   512
#define DOUT  128

// padded row counts (one extra M-tile so GEMM loaders need no bounds checks)
#define T_PAD 200064
#define O_PAD 50048

// ---------------- device scratch (allocation-free rule) -----------------------
__device__ __half  g_objh [(size_t)O_N * DIN];    // obj fp16 (indexed, no pad needed)
__device__ __half  g_predh[(size_t)T_PAD * DIN];  // pred fp16 (padded)
__device__ __half  g_h    [(size_t)T_PAD * 512];  // [T, 512] fp16 (padded)
__device__ float   g_pool [(size_t)O_N * HID];    // fp32 accum
__device__ __half  g_pool16[(size_t)O_PAD * 512]; // pooled fp16 (padded)
__device__ __half  g_h2   [(size_t)O_PAD * 512];  // [O, 512] fp16 (padded)
__device__ float   g_cnt  [O_N];
__device__ __half  g_bt1[(size_t)512  * 384];     // [N,K] fp16 (W1a^T)
__device__ __half  g_bt2[(size_t)1152 * 512];     // [N,K] fp16 (W1b^T)
__device__ __half  g_bt3[(size_t)512  * 512];     // [N,K] fp16 (W2a^T)
__device__ __half  g_bt4[(size_t)128  * 512];     // [N,K] fp16 (W2b^T)

// ---------------- PTX helpers -------------------------------------------------
__device__ __forceinline__ uint32_t smem_u32(const void* p) {
    uint32_t a;
    asm("{ .reg .u64 t; cvta.to.shared.u64 t, %1; cvt.u32.u64 %0, t; }" : "=r"(a) : "l"(p));
    return a;
}
__device__ __forceinline__ void cp_async16(uint32_t dst, const void* src) {
    asm volatile("cp.async.cg.shared.global [%0], [%1], 16;"
                 :: "r"(dst), "l"(src));
}
__device__ __forceinline__ void ldm_x4(uint32_t& r0, uint32_t& r1, uint32_t& r2,
                                       uint32_t& r3, uint32_t addr) {
    asm volatile("ldmatrix.sync.aligned.m8n8.x4.shared.b16 {%0,%1,%2,%3}, [%4];"
                 : "=r"(r0), "=r"(r1), "=r"(r2), "=r"(r3) : "r"(addr));
}
__device__ __forceinline__ void mma_f16(float* c, const uint32_t* a, const uint32_t* b) {
    asm volatile("mma.sync.aligned.m16n8k16.row.col.f32.f16.f16.f32 "
                 "{%0,%1,%2,%3}, {%4,%5,%6,%7}, {%8,%9}, {%0,%1,%2,%3};"
                 : "+f"(c[0]), "+f"(c[1]), "+f"(c[2]), "+f"(c[3])
                 : "r"(a[0]), "r"(a[1]), "r"(a[2]), "r"(a[3]), "r"(b[0]), "r"(b[1]));
}
__device__ __forceinline__ void red_add2(float* p, float a, float b) {
    asm volatile("red.global.add.v2.f32 [%0], {%1,%2};"
                 :: "l"(p), "f"(a), "f"(b) : "memory");
}

// ---------------- prep 1: zero pooled/cnt + obj/pred fp32->fp16 ----------------
__global__ void prep1(const float4* __restrict__ obj, __half2* __restrict__ objh,
                      const float4* __restrict__ pred, __half2* __restrict__ predh,
                      float4* __restrict__ pool4, float* __restrict__ cnt) {
    int i = blockIdx.x * 256 + threadIdx.x;
    const int n4_obj  = O_N * DIN / 4;
    const int n4_pred = T_N * DIN / 4;
    const int n4_pool = O_N * HID / 4;
    if (i < n4_pool) pool4[i] = make_float4(0.f, 0.f, 0.f, 0.f);
    if (i < O_N) cnt[i] = 0.f;
    if (i < n4_obj) {
        float4 v = obj[i];
        objh[2*i]   = __halves2half2(__float2half_rn(v.x), __float2half_rn(v.y));
        objh[2*i+1] = __halves2half2(__float2half_rn(v.z), __float2half_rn(v.w));
    }
    if (i < n4_pred) {
        float4 v = pred[i];
        predh[2*i]   = __halves2half2(__float2half_rn(v.x), __float2half_rn(v.y));
        predh[2*i+1] = __halves2half2(__float2half_rn(v.z), __float2half_rn(v.w));
    }
}

// ---------------- prep 2: all weight transposes + degree counts ----------------
__global__ void prep2(const float* __restrict__ W1a, const float* __restrict__ W1b,
                      const float* __restrict__ W2a, const float* __restrict__ W2b,
                      __half* __restrict__ bt1, __half* __restrict__ bt2,
                      __half* __restrict__ bt3, __half* __restrict__ bt4,
                      const int* __restrict__ edges, float* __restrict__ cnt) {
    int i = blockIdx.x * 256 + threadIdx.x;
    if (i < T_N) {
        atomicAdd(&cnt[edges[2*i]], 1.0f);
        atomicAdd(&cnt[edges[2*i + 1]], 1.0f);
    }
    const float* W; __half* Bt; int K, N, idx;
    if (i < 196608)       { W = W1a; Bt = bt1; K = 384; N = 512;  idx = i; }
    else if (i < 786432)  { W = W1b; Bt = bt2; K = 512; N = 1152; idx = i - 196608; }
    else if (i < 1048576) { W = W2a; Bt = bt3; K = 512; N = 512;  idx = i - 786432; }
    else if (i < 1114112) { W = W2b; Bt = bt4; K = 512; N = 128;  idx = i - 1048576; }
    else return;
    int n = idx / K, k = idx - n * K;
    Bt[idx] = __float2half_rn(W[(size_t)k * N + n]);
}

// pooled/counts -> plain fp16
__global__ void pscale_conv(const float4* __restrict__ pooled, const float* __restrict__ cnt,
                            __half* __restrict__ p16) {
    int i = blockIdx.x * 256 + threadIdx.x;
    if (i >= O_N * (HID / 4)) return;
    int r = i >> 7;
    float c = fminf(fmaxf(cnt[r], 1.0f), 50000.0f);
    float s = 1.0f / c;
    float4 v = pooled[i];
    __half* row = p16 + (size_t)r * 512;
    int c0 = (i & 127) * 4;
    *(__half2*)(row + c0)     = __halves2half2(__float2half_rn(v.x * s), __float2half_rn(v.y * s));
    *(__half2*)(row + c0 + 2) = __halves2half2(__float2half_rn(v.z * s), __float2half_rn(v.w * s));
}

// ---------------- shared GEMM machinery ---------------------------------------
// CTA 128x128, 4 warps (64x64), BK=64, 2-stage pipeline, 128B-row swizzle.
// R11 layout: full 16-load burst BEFORE compute (bursts drain while compute
// runs; interleaving loads into the ks loop conflicts with LDSM in L1TEX).
#define BM 128
#define BN 128
#define BK 64
#define STG 2
#define STG_BYTES 32768

struct AddrCtx {
    uint32_t rbA[4], rbB[4], xoff[4];
};
__device__ __forceinline__ void make_ctx(AddrCtx& cx, int wm, int wn, int lane) {
    #pragma unroll
    for (int mf = 0; mf < 4; mf++) cx.rbA[mf] = (uint32_t)((wm + mf * 16 + (lane & 15)) * 128);
    #pragma unroll
    for (int bi = 0; bi < 4; bi++) cx.rbB[bi] = (uint32_t)((wn + bi * 16 + (lane & 15)) * 128);
    #pragma unroll
    for (int ks = 0; ks < 4; ks++)
        cx.xoff[ks] = (uint32_t)((((ks * 2 + (lane >> 4)) ^ (lane & 7))) << 4);
}

__device__ __forceinline__ void compute_chunk(uint32_t sa, uint32_t sb,
                                              const AddrCtx& cx,
                                              float acc[4][8][4]) {
    #pragma unroll
    for (int ks = 0; ks < 4; ks++) {
        const uint32_t sax = sa + cx.xoff[ks];
        const uint32_t sbx = sb + cx.xoff[ks];
        uint32_t a[4][4], b[8][2];
        #pragma unroll
        for (int mf = 0; mf < 4; mf++)
            ldm_x4(a[mf][0], a[mf][1], a[mf][2], a[mf][3], sax + cx.rbA[mf]);
        #pragma unroll
        for (int bi = 0; bi < 4; bi++) {
            uint32_t r0, r1, r2, r3;
            ldm_x4(r0, r1, r2, r3, sbx + cx.rbB[bi]);
            b[bi*2+0][0] = r0; b[bi*2+0][1] = r2;
            b[bi*2+1][0] = r1; b[bi*2+1][1] = r3;
        }
        #pragma unroll
        for (int mf = 0; mf < 4; mf++)
            #pragma unroll
            for (int nf = 0; nf < 8; nf++)
                mma_f16(acc[mf][nf], a[mf], b[nf]);
    }
}

// ---------------- GEMM1 with fused edge gather --------------------------------
__global__ void __launch_bounds__(128, 3)
g1_gemm(const __half* __restrict__ objh, const __half* __restrict__ predh,
        const int* __restrict__ edges, const __half* __restrict__ Bt,
        const float* __restrict__ bias, __half* __restrict__ outh)
{
    extern __shared__ char smem[];
    const int tid  = threadIdx.x;
    const int wid  = tid >> 5;
    const int lane = tid & 31;
    const int m0   = blockIdx.y * BM;
    const int n0   = blockIdx.x * BN;
    const int wm   = (wid >> 1) * 64;
    const int wn   = (wid & 1) * 64;
    const int M    = T_N;
    constexpr int Kc = 384;
    constexpr int NC = Kc / BK;   // 6
    const uint32_t sbase = smem_u32(smem);

    int2* esm = (int2*)(smem + STG * STG_BYTES);
    {
        int gr = m0 + tid;
        esm[tid] = (gr < M) ? *(const int2*)&edges[2*gr] : make_int2(0, 0);
    }
    __syncthreads();

    AddrCtx cx; make_ctx(cx, wm, wn, lane);
    const int lrow = tid >> 3, lch = tid & 7;
    const uint32_t off0 = (uint32_t)(lrow * 128 + ((lch ^ (lrow & 7)) << 4));
    const __half* bBase = Bt + (size_t)(n0 + lrow) * Kc + lch * 8;

    float acc[4][8][4];
    #pragma unroll
    for (int i = 0; i < 4; i++)
        #pragma unroll
        for (int j = 0; j < 8; j++)
            #pragma unroll
            for (int k = 0; k < 4; k++) acc[i][j][k] = 0.f;

    auto ld_tile = [&](int it, int buf) {
        const int kp  = it * BK;
        const int reg = kp >> 7;          // 0: obj[s], 1: pred, 2: obj[o]
        const int kc  = (kp & 127) + lch * 8;
        uint32_t sa = sbase + buf * STG_BYTES;
        uint32_t sb = sa + 16384;
        #pragma unroll
        for (int t = 0; t < 8; t++) {
            int row = lrow + t * 16;
            const __half* src;
            if (reg == 0)      src = objh  + (size_t)esm[row].x * DIN + kc;
            else if (reg == 1) src = predh + (size_t)(m0 + row) * DIN + kc;
            else               src = objh  + (size_t)esm[row].y * DIN + kc;
            cp_async16(sa + off0 + t * 2048, src);
        }
        const __half* pb = bBase + kp;
        #pragma unroll
        for (int t = 0; t < 8; t++) {
            cp_async16(sb + off0 + t * 2048, pb);
            pb += 16 * Kc;
        }
    };

    ld_tile(0, 0);
    asm volatile("cp.async.commit_group;" ::: "memory");
    #pragma unroll
    for (int it = 0; it < NC; it++) {
        asm volatile("cp.async.wait_group 0;" ::: "memory");
        __syncthreads();
        if (it + 1 < NC) ld_tile(it + 1, (it + 1) & 1);
        asm volatile("cp.async.commit_group;" ::: "memory");
        uint32_t sa = sbase + (it & 1) * STG_BYTES;
        compute_chunk(sa, sa + 16384, cx, acc);
    }

    float bc[8][2];
    #pragma unroll
    for (int nf = 0; nf < 8; nf++) {
        float2 bv = __ldg((const float2*)&bias[n0 + wn + nf * 8 + (lane & 3) * 2]);
        bc[nf][0] = bv.x; bc[nf][1] = bv.y;
    }
    #pragma unroll
    for (int mf = 0; mf < 4; mf++)
        #pragma unroll
        for (int rh = 0; rh < 2; rh++) {
            const int gr = m0 + wm + mf * 16 + (lane >> 2) + rh * 8;
            if (gr >= M) continue;
            #pragma unroll
            for (int nf = 0; nf < 8; nf++) {
                const int col = n0 + wn + nf * 8 + (lane & 3) * 2;
                float v0 = fmaxf(acc[mf][nf][rh*2+0] + bc[nf][0], 0.f);
                float v1 = fmaxf(acc[mf][nf][rh*2+1] + bc[nf][1], 0.f);
                *(__half2*)&outh[(size_t)gr * HID + col] =
                    __halves2half2(__float2half_rn(v0), __float2half_rn(v1));
            }
        }
}

// ---------------- generic GEMM (K = strideA = 512, compile-time) ---------------
// A padded beyond M (garbage rows discarded by guarded epilogue).
// EPI 0: fp32 store    EPI 2: GEMM2 router    EPI 3: plain fp16 store
template<int EPI>
__global__ void __launch_bounds__(128, 3)
mma_gemm(const __half* __restrict__ A, const __half* __restrict__ Bt,
         const float* __restrict__ bias, float* __restrict__ outf,
         __half* __restrict__ outh,
         int M, int ostride,
         const int* __restrict__ edges, float* __restrict__ pooled,
         float* __restrict__ newp)
{
    extern __shared__ char smem[];
    constexpr int Kc = 512;
    constexpr int NC = Kc / BK;   // 8
    const int tid  = threadIdx.x;
    const int wid  = tid >> 5;
    const int lane = tid & 31;
    const int m0   = blockIdx.y * BM;
    const int n0   = blockIdx.x * BN;
    const int wm   = (wid >> 1) * 64;
    const int wn   = (wid & 1) * 64;
    const uint32_t sbase = smem_u32(smem);

    AddrCtx cx; make_ctx(cx, wm, wn, lane);
    const int lrow = tid >> 3, lch = tid & 7;
    const uint32_t off0 = (uint32_t)(lrow * 128 + ((lch ^ (lrow & 7)) << 4));
    const __half* aBase = A  + (size_t)(m0 + lrow) * Kc + lch * 8;
    const __half* bBase = Bt + (size_t)(n0 + lrow) * Kc + lch * 8;

    float acc[4][8][4];
    #pragma unroll
    for (int i = 0; i < 4; i++)
        #pragma unroll
        for (int j = 0; j < 8; j++)
            #pragma unroll
            for (int k = 0; k < 4; k++) acc[i][j][k] = 0.f;

    auto ld_tile = [&](int it, int buf) {
        const int kp = it * BK;
        uint32_t sa = sbase + buf * STG_BYTES;
        uint32_t sb = sa + 16384;
        const __half* pa = aBase + kp;
        const __half* pb = bBase + kp;
        #pragma unroll
        for (int t = 0; t < 8; t++) {
            cp_async16(sa + off0 + t * 2048, pa);
            pa += 16 * Kc;
        }
        #pragma unroll
        for (int t = 0; t < 8; t++) {
            cp_async16(sb + off0 + t * 2048, pb);
            pb += 16 * Kc;
        }
    };

    ld_tile(0, 0);
    asm volatile("cp.async.commit_group;" ::: "memory");
    #pragma unroll
    for (int it = 0; it < NC; it++) {
        asm volatile("cp.async.wait_group 0;" ::: "memory");
        __syncthreads();
        if (it + 1 < NC) ld_tile(it + 1, (it + 1) & 1);
        asm volatile("cp.async.commit_group;" ::: "memory");
        uint32_t sa = sbase + (it & 1) * STG_BYTES;
        compute_chunk(sa, sa + 16384, cx, acc);
    }

    float bc[8][2];
    #pragma unroll
    for (int nf = 0; nf < 8; nf++) {
        float2 bv = __ldg((const float2*)&bias[n0 + wn + nf * 8 + (lane & 3) * 2]);
        bc[nf][0] = bv.x; bc[nf][1] = bv.y;
    }

    #pragma unroll
    for (int mf = 0; mf < 4; mf++)
        #pragma unroll
        for (int rh = 0; rh < 2; rh++) {
            const int gr = m0 + wm + mf * 16 + (lane >> 2) + rh * 8;
            if (gr >= M) continue;
            int es = 0, eo = 0;
            if (EPI == 2) { es = edges[2*gr]; eo = edges[2*gr + 1]; }
            #pragma unroll
            for (int nf = 0; nf < 8; nf++) {
                const int col = n0 + wn + nf * 8 + (lane & 3) * 2;
                float v0 = fmaxf(acc[mf][nf][rh*2+0] + bc[nf][0], 0.f);
                float v1 = fmaxf(acc[mf][nf][rh*2+1] + bc[nf][1], 0.f);
                if (EPI == 0) {
                    *(float2*)&outf[(size_t)gr * ostride + col] = make_float2(v0, v1);
                } else if (EPI == 3) {
                    *(__half2*)&outh[(size_t)gr * ostride + col] =
                        __halves2half2(__float2half_rn(v0), __float2half_rn(v1));
                } else {
                    if (col < HID) {
                        red_add2(&pooled[(size_t)es * HID + col], v0, v1);
                    } else if (col < HID + DOUT) {
                        *(float2*)&newp[(size_t)gr * DOUT + (col - HID)] = make_float2(v0, v1);
                    } else {
                        red_add2(&pooled[(size_t)eo * HID + (col - HID - DOUT)], v0, v1);
                    }
                }
            }
        }
}

// ---------------- launch ------------------------------------------------------
// 7 launches; GEMM2 is launch #4 (the profiled slot).
extern "C" void kernel_launch(void* const* d_in, const int* in_sizes, int n_in,
                              void* d_out, int out_size) {
    const float* obj  = (const float*)d_in[0];
    const float* pred = (const float*)d_in[1];
    const int*   edges= (const int*)  d_in[2];
    const float* W1a  = (const float*)d_in[3];
    const float* b1a  = (const float*)d_in[4];
    const float* W1b  = (const float*)d_in[5];
    const float* b1b  = (const float*)d_in[6];
    const float* W2a  = (const float*)d_in[7];
    const float* b2a  = (const float*)d_in[8];
    const float* W2b  = (const float*)d_in[9];
    const float* b2b  = (const float*)d_in[10];

    float* out     = (float*)d_out;
    float* new_obj = out;                       // [O, 128]
    float* new_p   = out + (size_t)O_N * DOUT;  // [T, 128]

    __half *objh, *predh, *h16, *p16, *h2, *bt1, *bt2, *bt3, *bt4;
    float *pooled, *cnt;
    cudaGetSymbolAddress((void**)&objh,   g_objh);
    cudaGetSymbolAddress((void**)&predh,  g_predh);
    cudaGetSymbolAddress((void**)&h16,    g_h);
    cudaGetSymbolAddress((void**)&pooled, g_pool);
    cudaGetSymbolAddress((void**)&p16,    g_pool16);
    cudaGetSymbolAddress((void**)&h2,     g_h2);
    cudaGetSymbolAddress((void**)&cnt,    g_cnt);
    cudaGetSymbolAddress((void**)&bt1,    g_bt1);
    cudaGetSymbolAddress((void**)&bt2,    g_bt2);
    cudaGetSymbolAddress((void**)&bt3,    g_bt3);
    cudaGetSymbolAddress((void**)&bt4,    g_bt4);

    const int SMEM_G  = STG * STG_BYTES;          // 65536
    const int SMEM_G1 = SMEM_G + 128 * 8;         // + edge cache (1 KB)
    cudaFuncSetAttribute((const void*)g1_gemm,     cudaFuncAttributeMaxDynamicSharedMemorySize, SMEM_G1);
    cudaFuncSetAttribute((const void*)mma_gemm<0>, cudaFuncAttributeMaxDynamicSharedMemorySize, SMEM_G);
    cudaFuncSetAttribute((const void*)mma_gemm<2>, cudaFuncAttributeMaxDynamicSharedMemorySize, SMEM_G);
    cudaFuncSetAttribute((const void*)mma_gemm<3>, cudaFuncAttributeMaxDynamicSharedMemorySize, SMEM_G);

    const int MT_T = (T_N + 127) / 128;   // 1563
    const int MT_O = (O_N + 127) / 128;   // 391

    // 1: zero pooled/cnt + obj/pred fp16 converts
    {   int span = T_N * DIN / 4;   // 6.4M
        prep1<<<(span + 255) / 256, 256>>>(
            (const float4*)obj, (__half2*)objh,
            (const float4*)pred, (__half2*)predh,
            (float4*)pooled, cnt); }

    // 2: all weight transposes + degree counts
    prep2<<<(1114112 + 255) / 256, 256>>>(W1a, W1b, W2a, W2b,
                                          bt1, bt2, bt3, bt4, edges, cnt);

    // 3: GEMM1 (fused gather)
    g1_gemm<<<dim3(4, MT_T), 128, SMEM_G1>>>(objh, predh, edges, bt1, b1a, h16);

    // 4: GEMM2 (scatter s/o + new_p)   <-- profiled slot
    mma_gemm<2><<<dim3(9, MT_T), 128, SMEM_G>>>(
        h16, bt2, b1b, nullptr, nullptr,
        T_N, 0, edges, pooled, new_p);

    // 5: pooled scale + fp16
    pscale_conv<<<(O_N * (HID / 4) + 255) / 256, 256>>>((const float4*)pooled, cnt, p16);

    // 6: GEMM3
    mma_gemm<3><<<dim3(4, MT_O), 128, SMEM_G>>>(
        p16, bt3, b2a, nullptr, h2,
        O_N, HID, nullptr, nullptr, nullptr);

    // 7: GEMM4
    mma_gemm<0><<<dim3(1, MT_O), 128, SMEM_G>>>(
        h2, bt4, b2b, new_obj, nullptr,
        O_N, DOUT, nullptr, nullptr, nullptr);
}

// round 14
// speedup vs baseline: 1.1149x; 1.0629x over previous
#include <cuda_runtime.h>
#include <cuda_fp16.h>
#include <cstdint>

#define O_N   50000
#define T_N   200000
#define DIN   128
#define HID   512
#define DOUT  128

// padded row counts (one extra M-tile so GEMM loaders need no bounds checks)
#define T_PAD 200064
#define O_PAD 50048

// ---------------- device scratch (allocation-free rule) -----------------------
__device__ __half  g_objh [(size_t)O_N * DIN];    // obj fp16 (indexed, no pad needed)
__device__ __half  g_predh[(size_t)T_PAD * DIN];  // pred fp16 (padded)
__device__ __half  g_h    [(size_t)T_PAD * 512];  // [T, 512] fp16 (padded)
__device__ float   g_pool [(size_t)O_N * HID];    // fp32 accum
__device__ __half  g_pool16[(size_t)O_PAD * 512]; // pooled fp16 (padded)
__device__ __half  g_h2   [(size_t)O_PAD * 512];  // [O, 512] fp16 (padded)
__device__ float   g_cnt  [O_N];
__device__ __half  g_bt1[(size_t)512  * 384];     // [N,K] fp16 (W1a^T)
__device__ __half  g_bt2[(size_t)1152 * 512];     // [N,K] fp16 (W1b^T)
__device__ __half  g_bt3[(size_t)512  * 512];     // [N,K] fp16 (W2a^T)
__device__ __half  g_bt4[(size_t)128  * 512];     // [N,K] fp16 (W2b^T)

// ---------------- PTX helpers -------------------------------------------------
__device__ __forceinline__ uint32_t smem_u32(const void* p) {
    uint32_t a;
    asm("{ .reg .u64 t; cvta.to.shared.u64 t, %1; cvt.u32.u64 %0, t; }" : "=r"(a) : "l"(p));
    return a;
}
__device__ __forceinline__ void cp_async16(uint32_t dst, const void* src) {
    asm volatile("cp.async.cg.shared.global [%0], [%1], 16;"
                 :: "r"(dst), "l"(src));
}
__device__ __forceinline__ void pf_l2(const void* p) {
    asm volatile("prefetch.global.L2 [%0];" :: "l"(p));
}
__device__ __forceinline__ void ldm_x4(uint32_t& r0, uint32_t& r1, uint32_t& r2,
                                       uint32_t& r3, uint32_t addr) {
    asm volatile("ldmatrix.sync.aligned.m8n8.x4.shared.b16 {%0,%1,%2,%3}, [%4];"
                 : "=r"(r0), "=r"(r1), "=r"(r2), "=r"(r3) : "r"(addr));
}
__device__ __forceinline__ void mma_f16(float* c, const uint32_t* a, const uint32_t* b) {
    asm volatile("mma.sync.aligned.m16n8k16.row.col.f32.f16.f16.f32 "
                 "{%0,%1,%2,%3}, {%4,%5,%6,%7}, {%8,%9}, {%0,%1,%2,%3};"
                 : "+f"(c[0]), "+f"(c[1]), "+f"(c[2]), "+f"(c[3])
                 : "r"(a[0]), "r"(a[1]), "r"(a[2]), "r"(a[3]), "r"(b[0]), "r"(b[1]));
}
__device__ __forceinline__ void red_add2(float* p, float a, float b) {
    asm volatile("red.global.add.v2.f32 [%0], {%1,%2};"
                 :: "l"(p), "f"(a), "f"(b) : "memory");
}

// ---------------- prep 1: zero pooled/cnt + obj/pred fp32->fp16 ----------------
__global__ void prep1(const float4* __restrict__ obj, __half2* __restrict__ objh,
                      const float4* __restrict__ pred, __half2* __restrict__ predh,
                      float4* __restrict__ pool4, float* __restrict__ cnt) {
    int i = blockIdx.x * 256 + threadIdx.x;
    const int n4_obj  = O_N * DIN / 4;
    const int n4_pred = T_N * DIN / 4;
    const int n4_pool = O_N * HID / 4;
    if (i < n4_pool) pool4[i] = make_float4(0.f, 0.f, 0.f, 0.f);
    if (i < O_N) cnt[i] = 0.f;
    if (i < n4_obj) {
        float4 v = obj[i];
        objh[2*i]   = __halves2half2(__float2half_rn(v.x), __float2half_rn(v.y));
        objh[2*i+1] = __halves2half2(__float2half_rn(v.z), __float2half_rn(v.w));
    }
    if (i < n4_pred) {
        float4 v = pred[i];
        predh[2*i]   = __halves2half2(__float2half_rn(v.x), __float2half_rn(v.y));
        predh[2*i+1] = __halves2half2(__float2half_rn(v.z), __float2half_rn(v.w));
    }
}

// ---------------- prep 2: all weight transposes + degree counts ----------------
__global__ void prep2(const float* __restrict__ W1a, const float* __restrict__ W1b,
                      const float* __restrict__ W2a, const float* __restrict__ W2b,
                      __half* __restrict__ bt1, __half* __restrict__ bt2,
                      __half* __restrict__ bt3, __half* __restrict__ bt4,
                      const int* __restrict__ edges, float* __restrict__ cnt) {
    int i = blockIdx.x * 256 + threadIdx.x;
    if (i < T_N) {
        atomicAdd(&cnt[edges[2*i]], 1.0f);
        atomicAdd(&cnt[edges[2*i + 1]], 1.0f);
    }
    const float* W; __half* Bt; int K, N, idx;
    if (i < 196608)       { W = W1a; Bt = bt1; K = 384; N = 512;  idx = i; }
    else if (i < 786432)  { W = W1b; Bt = bt2; K = 512; N = 1152; idx = i - 196608; }
    else if (i < 1048576) { W = W2a; Bt = bt3; K = 512; N = 512;  idx = i - 786432; }
    else if (i < 1114112) { W = W2b; Bt = bt4; K = 512; N = 128;  idx = i - 1048576; }
    else return;
    int n = idx / K, k = idx - n * K;
    Bt[idx] = __float2half_rn(W[(size_t)k * N + n]);
}

// pooled/counts -> plain fp16
__global__ void pscale_conv(const float4* __restrict__ pooled, const float* __restrict__ cnt,
                            __half* __restrict__ p16) {
    int i = blockIdx.x * 256 + threadIdx.x;
    if (i >= O_N * (HID / 4)) return;
    int r = i >> 7;
    float c = fminf(fmaxf(cnt[r], 1.0f), 50000.0f);
    float s = 1.0f / c;
    float4 v = pooled[i];
    __half* row = p16 + (size_t)r * 512;
    int c0 = (i & 127) * 4;
    *(__half2*)(row + c0)     = __halves2half2(__float2half_rn(v.x * s), __float2half_rn(v.y * s));
    *(__half2*)(row + c0 + 2) = __halves2half2(__float2half_rn(v.z * s), __float2half_rn(v.w * s));
}

// ---------------- shared GEMM machinery ---------------------------------------
// CTA 128x128, 4 warps (64x64), BK=64, 2-stage pipeline, 128B-row swizzle.
// R11 layout (verified best): full 16-load burst BEFORE compute. New: the A
// stream is L2-prefetched one further chunk ahead (distance 2 from compute).
#define BM 128
#define BN 128
#define BK 64
#define STG 2
#define STG_BYTES 32768

struct AddrCtx {
    uint32_t rbA[4], rbB[4], xoff[4];
};
__device__ __forceinline__ void make_ctx(AddrCtx& cx, int wm, int wn, int lane) {
    #pragma unroll
    for (int mf = 0; mf < 4; mf++) cx.rbA[mf] = (uint32_t)((wm + mf * 16 + (lane & 15)) * 128);
    #pragma unroll
    for (int bi = 0; bi < 4; bi++) cx.rbB[bi] = (uint32_t)((wn + bi * 16 + (lane & 15)) * 128);
    #pragma unroll
    for (int ks = 0; ks < 4; ks++)
        cx.xoff[ks] = (uint32_t)((((ks * 2 + (lane >> 4)) ^ (lane & 7))) << 4);
}

__device__ __forceinline__ void compute_chunk(uint32_t sa, uint32_t sb,
                                              const AddrCtx& cx,
                                              float acc[4][8][4]) {
    #pragma unroll
    for (int ks = 0; ks < 4; ks++) {
        const uint32_t sax = sa + cx.xoff[ks];
        const uint32_t sbx = sb + cx.xoff[ks];
        uint32_t a[4][4], b[8][2];
        #pragma unroll
        for (int mf = 0; mf < 4; mf++)
            ldm_x4(a[mf][0], a[mf][1], a[mf][2], a[mf][3], sax + cx.rbA[mf]);
        #pragma unroll
        for (int bi = 0; bi < 4; bi++) {
            uint32_t r0, r1, r2, r3;
            ldm_x4(r0, r1, r2, r3, sbx + cx.rbB[bi]);
            b[bi*2+0][0] = r0; b[bi*2+0][1] = r2;
            b[bi*2+1][0] = r1; b[bi*2+1][1] = r3;
        }
        #pragma unroll
        for (int mf = 0; mf < 4; mf++)
            #pragma unroll
            for (int nf = 0; nf < 8; nf++)
                mma_f16(acc[mf][nf], a[mf], b[nf]);
    }
}

// ---------------- GEMM1 with fused edge gather --------------------------------
__global__ void __launch_bounds__(128, 3)
g1_gemm(const __half* __restrict__ objh, const __half* __restrict__ predh,
        const int* __restrict__ edges, const __half* __restrict__ Bt,
        const float* __restrict__ bias, __half* __restrict__ outh)
{
    extern __shared__ char smem[];
    const int tid  = threadIdx.x;
    const int wid  = tid >> 5;
    const int lane = tid & 31;
    const int m0   = blockIdx.y * BM;
    const int n0   = blockIdx.x * BN;
    const int wm   = (wid >> 1) * 64;
    const int wn   = (wid & 1) * 64;
    const int M    = T_N;
    const int Kc   = 384;
    const uint32_t sbase = smem_u32(smem);

    int2* esm = (int2*)(smem + STG * STG_BYTES);
    {
        int gr = m0 + tid;
        esm[tid] = (gr < M) ? *(const int2*)&edges[2*gr] : make_int2(0, 0);
    }
    __syncthreads();

    AddrCtx cx; make_ctx(cx, wm, wn, lane);
    const int lrow = tid >> 3, lch = tid & 7;
    const uint32_t off0 = (uint32_t)(lrow * 128 + ((lch ^ (lrow & 7)) << 4));
    const __half* bBase = Bt + (size_t)(n0 + lrow) * Kc + lch * 8;

    float acc[4][8][4];
    #pragma unroll
    for (int i = 0; i < 4; i++)
        #pragma unroll
        for (int j = 0; j < 8; j++)
            #pragma unroll
            for (int k = 0; k < 4; k++) acc[i][j][k] = 0.f;

    // A-source resolver for row (0..127) at chunk `it`
    auto a_src = [&](int it, int row) -> const __half* {
        const int kp  = it * BK;
        const int reg = kp >> 7;
        const int kc  = (kp & 127) + lch * 8;
        if (reg == 0)      return objh  + (size_t)esm[row].x * DIN + kc;
        else if (reg == 1) return predh + (size_t)(m0 + row) * DIN + kc;
        else               return objh  + (size_t)esm[row].y * DIN + kc;
    };

    auto ld_tile = [&](int it, int buf) {
        uint32_t sa = sbase + buf * STG_BYTES;
        uint32_t sb = sa + 16384;
        #pragma unroll
        for (int t = 0; t < 8; t++)
            cp_async16(sa + off0 + t * 2048, a_src(it, lrow + t * 16));
        const __half* pb = bBase + it * BK;
        #pragma unroll
        for (int t = 0; t < 8; t++) {
            cp_async16(sb + off0 + t * 2048, pb);
            pb += 16 * Kc;
        }
        // L2-prefetch the A rows of the NEXT chunk (distance 2 from compute)
        if (it + 1 < 6) {
            #pragma unroll
            for (int t = 0; t < 8; t++)
                pf_l2(a_src(it + 1, lrow + t * 16));
        }
    };

    const int NC = Kc / BK;   // 6
    ld_tile(0, 0);
    asm volatile("cp.async.commit_group;" ::: "memory");
    for (int it = 0; it < NC; it++) {
        asm volatile("cp.async.wait_group 0;" ::: "memory");
        __syncthreads();
        if (it + 1 < NC) ld_tile(it + 1, (it + 1) & 1);
        asm volatile("cp.async.commit_group;" ::: "memory");
        uint32_t sa = sbase + (it & 1) * STG_BYTES;
        compute_chunk(sa, sa + 16384, cx, acc);
    }

    float bc[8][2];
    #pragma unroll
    for (int nf = 0; nf < 8; nf++) {
        float2 bv = __ldg((const float2*)&bias[n0 + wn + nf * 8 + (lane & 3) * 2]);
        bc[nf][0] = bv.x; bc[nf][1] = bv.y;
    }
    #pragma unroll
    for (int mf = 0; mf < 4; mf++)
        #pragma unroll
        for (int rh = 0; rh < 2; rh++) {
            const int gr = m0 + wm + mf * 16 + (lane >> 2) + rh * 8;
            if (gr >= M) continue;
            #pragma unroll
            for (int nf = 0; nf < 8; nf++) {
                const int col = n0 + wn + nf * 8 + (lane & 3) * 2;
                float v0 = fmaxf(acc[mf][nf][rh*2+0] + bc[nf][0], 0.f);
                float v1 = fmaxf(acc[mf][nf][rh*2+1] + bc[nf][1], 0.f);
                *(__half2*)&outh[(size_t)gr * HID + col] =
                    __halves2half2(__float2half_rn(v0), __float2half_rn(v1));
            }
        }
}

// ---------------- generic GEMM -------------------------------------------------
// A padded beyond M (garbage rows discarded by guarded epilogue).
// EPI 0: fp32 store    EPI 2: GEMM2 router    EPI 3: plain fp16 store
template<int EPI>
__global__ void __launch_bounds__(128, 3)
mma_gemm(const __half* __restrict__ A, const __half* __restrict__ Bt,
         const float* __restrict__ bias, float* __restrict__ outf,
         __half* __restrict__ outh,
         int M, int strideA, int Kc, int ostride,
         const int* __restrict__ edges, float* __restrict__ pooled,
         float* __restrict__ newp)
{
    extern __shared__ char smem[];
    const int tid  = threadIdx.x;
    const int wid  = tid >> 5;
    const int lane = tid & 31;
    const int m0   = blockIdx.y * BM;
    const int n0   = blockIdx.x * BN;
    const int wm   = (wid >> 1) * 64;
    const int wn   = (wid & 1) * 64;
    const uint32_t sbase = smem_u32(smem);

    AddrCtx cx; make_ctx(cx, wm, wn, lane);
    const int lrow = tid >> 3, lch = tid & 7;
    const uint32_t off0 = (uint32_t)(lrow * 128 + ((lch ^ (lrow & 7)) << 4));
    const __half* aBase = A  + (size_t)(m0 + lrow) * strideA + lch * 8;
    const __half* bBase = Bt + (size_t)(n0 + lrow) * Kc      + lch * 8;

    float acc[4][8][4];
    #pragma unroll
    for (int i = 0; i < 4; i++)
        #pragma unroll
        for (int j = 0; j < 8; j++)
            #pragma unroll
            for (int k = 0; k < 4; k++) acc[i][j][k] = 0.f;

    const int NC = Kc / BK;
    auto ld_tile = [&](int it, int buf) {
        const int kp = it * BK;
        uint32_t sa = sbase + buf * STG_BYTES;
        uint32_t sb = sa + 16384;
        const __half* pa = aBase + kp;
        const __half* pb = bBase + kp;
        #pragma unroll
        for (int t = 0; t < 8; t++) {
            cp_async16(sa + off0 + t * 2048, pa);
            pa += 16 * strideA;
        }
        #pragma unroll
        for (int t = 0; t < 8; t++) {
            cp_async16(sb + off0 + t * 2048, pb);
            pb += 16 * Kc;
        }
        // L2-prefetch the A stream of the NEXT chunk (distance 2 from compute)
        if (it + 1 < NC) {
            const __half* pf = aBase + kp + BK;
            #pragma unroll
            for (int t = 0; t < 8; t++) {
                pf_l2(pf);
                pf += 16 * strideA;
            }
        }
    };

    ld_tile(0, 0);
    asm volatile("cp.async.commit_group;" ::: "memory");
    for (int it = 0; it < NC; it++) {
        asm volatile("cp.async.wait_group 0;" ::: "memory");
        __syncthreads();
        if (it + 1 < NC) ld_tile(it + 1, (it + 1) & 1);
        asm volatile("cp.async.commit_group;" ::: "memory");
        uint32_t sa = sbase + (it & 1) * STG_BYTES;
        compute_chunk(sa, sa + 16384, cx, acc);
    }

    float bc[8][2];
    #pragma unroll
    for (int nf = 0; nf < 8; nf++) {
        float2 bv = __ldg((const float2*)&bias[n0 + wn + nf * 8 + (lane & 3) * 2]);
        bc[nf][0] = bv.x; bc[nf][1] = bv.y;
    }

    #pragma unroll
    for (int mf = 0; mf < 4; mf++)
        #pragma unroll
        for (int rh = 0; rh < 2; rh++) {
            const int gr = m0 + wm + mf * 16 + (lane >> 2) + rh * 8;
            if (gr >= M) continue;
            int es = 0, eo = 0;
            if (EPI == 2) { es = edges[2*gr]; eo = edges[2*gr + 1]; }
            #pragma unroll
            for (int nf = 0; nf < 8; nf++) {
                const int col = n0 + wn + nf * 8 + (lane & 3) * 2;
                float v0 = fmaxf(acc[mf][nf][rh*2+0] + bc[nf][0], 0.f);
                float v1 = fmaxf(acc[mf][nf][rh*2+1] + bc[nf][1], 0.f);
                if (EPI == 0) {
                    *(float2*)&outf[(size_t)gr * ostride + col] = make_float2(v0, v1);
                } else if (EPI == 3) {
                    *(__half2*)&outh[(size_t)gr * ostride + col] =
                        __halves2half2(__float2half_rn(v0), __float2half_rn(v1));
                } else {
                    if (col < HID) {
                        red_add2(&pooled[(size_t)es * HID + col], v0, v1);
                    } else if (col < HID + DOUT) {
                        *(float2*)&newp[(size_t)gr * DOUT + (col - HID)] = make_float2(v0, v1);
                    } else {
                        red_add2(&pooled[(size_t)eo * HID + (col - HID - DOUT)], v0, v1);
                    }
                }
            }
        }
}

// ---------------- launch ------------------------------------------------------
// 7 launches; GEMM2 is launch #4 (the profiled slot).
extern "C" void kernel_launch(void* const* d_in, const int* in_sizes, int n_in,
                              void* d_out, int out_size) {
    const float* obj  = (const float*)d_in[0];
    const float* pred = (const float*)d_in[1];
    const int*   edges= (const int*)  d_in[2];
    const float* W1a  = (const float*)d_in[3];
    const float* b1a  = (const float*)d_in[4];
    const float* W1b  = (const float*)d_in[5];
    const float* b1b  = (const float*)d_in[6];
    const float* W2a  = (const float*)d_in[7];
    const float* b2a  = (const float*)d_in[8];
    const float* W2b  = (const float*)d_in[9];
    const float* b2b  = (const float*)d_in[10];

    float* out     = (float*)d_out;
    float* new_obj = out;                       // [O, 128]
    float* new_p   = out + (size_t)O_N * DOUT;  // [T, 128]

    __half *objh, *predh, *h16, *p16, *h2, *bt1, *bt2, *bt3, *bt4;
    float *pooled, *cnt;
    cudaGetSymbolAddress((void**)&objh,   g_objh);
    cudaGetSymbolAddress((void**)&predh,  g_predh);
    cudaGetSymbolAddress((void**)&h16,    g_h);
    cudaGetSymbolAddress((void**)&pooled, g_pool);
    cudaGetSymbolAddress((void**)&p16,    g_pool16);
    cudaGetSymbolAddress((void**)&h2,     g_h2);
    cudaGetSymbolAddress((void**)&cnt,    g_cnt);
    cudaGetSymbolAddress((void**)&bt1,    g_bt1);
    cudaGetSymbolAddress((void**)&bt2,    g_bt2);
    cudaGetSymbolAddress((void**)&bt3,    g_bt3);
    cudaGetSymbolAddress((void**)&bt4,    g_bt4);

    const int SMEM_G  = STG * STG_BYTES;          // 65536
    const int SMEM_G1 = SMEM_G + 128 * 8;         // + edge cache (1 KB)
    cudaFuncSetAttribute((const void*)g1_gemm,     cudaFuncAttributeMaxDynamicSharedMemorySize, SMEM_G1);
    cudaFuncSetAttribute((const void*)mma_gemm<0>, cudaFuncAttributeMaxDynamicSharedMemorySize, SMEM_G);
    cudaFuncSetAttribute((const void*)mma_gemm<2>, cudaFuncAttributeMaxDynamicSharedMemorySize, SMEM_G);
    cudaFuncSetAttribute((const void*)mma_gemm<3>, cudaFuncAttributeMaxDynamicSharedMemorySize, SMEM_G);

    const int MT_T = (T_N + 127) / 128;   // 1563
    const int MT_O = (O_N + 127) / 128;   // 391

    // 1: zero pooled/cnt + obj/pred fp16 converts
    {   int span = T_N * DIN / 4;   // 6.4M
        prep1<<<(span + 255) / 256, 256>>>(
            (const float4*)obj, (__half2*)objh,
            (const float4*)pred, (__half2*)predh,
            (float4*)pooled, cnt); }

    // 2: all weight transposes + degree counts
    prep2<<<(1114112 + 255) / 256, 256>>>(W1a, W1b, W2a, W2b,
                                          bt1, bt2, bt3, bt4, edges, cnt);

    // 3: GEMM1 (fused gather)
    g1_gemm<<<dim3(4, MT_T), 128, SMEM_G1>>>(objh, predh, edges, bt1, b1a, h16);

    // 4: GEMM2 (scatter s/o + new_p)   <-- profiled slot
    mma_gemm<2><<<dim3(9, MT_T), 128, SMEM_G>>>(
        h16, bt2, b1b, nullptr, nullptr,
        T_N, 512, 512, 0, edges, pooled, new_p);

    // 5: pooled scale + fp16
    pscale_conv<<<(O_N * (HID / 4) + 255) / 256, 256>>>((const float4*)pooled, cnt, p16);

    // 6: GEMM3
    mma_gemm<3><<<dim3(4, MT_O), 128, SMEM_G>>>(
        p16, bt3, b2a, nullptr, h2,
        O_N, 512, 512, HID, nullptr, nullptr, nullptr);

    // 7: GEMM4
    mma_gemm<0><<<dim3(1, MT_O), 128, SMEM_G>>>(
        h2, bt4, b2b, new_obj, nullptr,
        O_N, 512, 512, DOUT, nullptr, nullptr, nullptr);
}

// round 15
// speedup vs baseline: 1.1435x; 1.0257x over previous
#include <cuda_runtime.h>
#include <cuda_fp16.h>
#include <cstdint>

#define O_N   50000
#define T_N   200000
#define DIN   128
#define HID   512
#define DOUT  128

// padded row counts (one extra M-tile so GEMM loaders need no bounds checks)
#define T_PAD 200064
#define O_PAD 50048

// ---------------- device scratch (allocation-free rule) -----------------------
__device__ __half  g_objh [(size_t)O_N * DIN];    // obj fp16 (indexed, no pad needed)
__device__ __half  g_predh[(size_t)T_PAD * DIN];  // pred fp16 (padded)
__device__ __half  g_h    [(size_t)T_PAD * 512];  // [T, 512] fp16 (padded)
__device__ float   g_pool [(size_t)O_N * HID];    // fp32 accum
__device__ __half  g_pool16[(size_t)O_PAD * 512]; // pooled fp16 (padded)
__device__ __half  g_h2   [(size_t)O_PAD * 512];  // [O, 512] fp16 (padded)
__device__ float   g_cnt  [O_N];
__device__ __half  g_bt1[(size_t)512  * 384];     // [N,K] fp16 (W1a^T)
__device__ __half  g_bt2[(size_t)1152 * 512];     // [N,K] fp16 (W1b^T)
__device__ __half  g_bt3[(size_t)512  * 512];     // [N,K] fp16 (W2a^T)
__device__ __half  g_bt4[(size_t)128  * 512];     // [N,K] fp16 (W2b^T)

// ---------------- PTX helpers -------------------------------------------------
__device__ __forceinline__ uint32_t smem_u32(const void* p) {
    uint32_t a;
    asm("{ .reg .u64 t; cvta.to.shared.u64 t, %1; cvt.u32.u64 %0, t; }" : "=r"(a) : "l"(p));
    return a;
}
__device__ __forceinline__ void cp_async16(uint32_t dst, const void* src) {
    asm volatile("cp.async.cg.shared.global [%0], [%1], 16;"
                 :: "r"(dst), "l"(src));
}
__device__ __forceinline__ void ldm_x4(uint32_t& r0, uint32_t& r1, uint32_t& r2,
                                       uint32_t& r3, uint32_t addr) {
    asm volatile("ldmatrix.sync.aligned.m8n8.x4.shared.b16 {%0,%1,%2,%3}, [%4];"
                 : "=r"(r0), "=r"(r1), "=r"(r2), "=r"(r3) : "r"(addr));
}
__device__ __forceinline__ void mma_f16(float* c, const uint32_t* a, const uint32_t* b) {
    asm volatile("mma.sync.aligned.m16n8k16.row.col.f32.f16.f16.f32 "
                 "{%0,%1,%2,%3}, {%4,%5,%6,%7}, {%8,%9}, {%0,%1,%2,%3};"
                 : "+f"(c[0]), "+f"(c[1]), "+f"(c[2]), "+f"(c[3])
                 : "r"(a[0]), "r"(a[1]), "r"(a[2]), "r"(a[3]), "r"(b[0]), "r"(b[1]));
}
__device__ __forceinline__ void red_add2(float* p, float a, float b) {
    asm volatile("red.global.add.v2.f32 [%0], {%1,%2};"
                 :: "l"(p), "f"(a), "f"(b) : "memory");
}

// ---------------- prep 1: zero pooled/cnt + obj/pred fp32->fp16 ----------------
__global__ void prep1(const float4* __restrict__ obj, __half2* __restrict__ objh,
                      const float4* __restrict__ pred, __half2* __restrict__ predh,
                      float4* __restrict__ pool4, float* __restrict__ cnt) {
    int i = blockIdx.x * 256 + threadIdx.x;
    const int n4_obj  = O_N * DIN / 4;
    const int n4_pred = T_N * DIN / 4;
    const int n4_pool = O_N * HID / 4;
    if (i < n4_pool) pool4[i] = make_float4(0.f, 0.f, 0.f, 0.f);
    if (i < O_N) cnt[i] = 0.f;
    if (i < n4_obj) {
        float4 v = obj[i];
        objh[2*i]   = __halves2half2(__float2half_rn(v.x), __float2half_rn(v.y));
        objh[2*i+1] = __halves2half2(__float2half_rn(v.z), __float2half_rn(v.w));
    }
    if (i < n4_pred) {
        float4 v = pred[i];
        predh[2*i]   = __halves2half2(__float2half_rn(v.x), __float2half_rn(v.y));
        predh[2*i+1] = __halves2half2(__float2half_rn(v.z), __float2half_rn(v.w));
    }
}

// ---------------- prep 2: all weight transposes + degree counts ----------------
__global__ void prep2(const float* __restrict__ W1a, const float* __restrict__ W1b,
                      const float* __restrict__ W2a, const float* __restrict__ W2b,
                      __half* __restrict__ bt1, __half* __restrict__ bt2,
                      __half* __restrict__ bt3, __half* __restrict__ bt4,
                      const int* __restrict__ edges, float* __restrict__ cnt) {
    int i = blockIdx.x * 256 + threadIdx.x;
    if (i < T_N) {
        atomicAdd(&cnt[edges[2*i]], 1.0f);
        atomicAdd(&cnt[edges[2*i + 1]], 1.0f);
    }
    const float* W; __half* Bt; int K, N, idx;
    if (i < 196608)       { W = W1a; Bt = bt1; K = 384; N = 512;  idx = i; }
    else if (i < 786432)  { W = W1b; Bt = bt2; K = 512; N = 1152; idx = i - 196608; }
    else if (i < 1048576) { W = W2a; Bt = bt3; K = 512; N = 512;  idx = i - 786432; }
    else if (i < 1114112) { W = W2b; Bt = bt4; K = 512; N = 128;  idx = i - 1048576; }
    else return;
    int n = idx / K, k = idx - n * K;
    Bt[idx] = __float2half_rn(W[(size_t)k * N + n]);
}

// pooled/counts -> plain fp16
__global__ void pscale_conv(const float4* __restrict__ pooled, const float* __restrict__ cnt,
                            __half* __restrict__ p16) {
    int i = blockIdx.x * 256 + threadIdx.x;
    if (i >= O_N * (HID / 4)) return;
    int r = i >> 7;
    float c = fminf(fmaxf(cnt[r], 1.0f), 50000.0f);
    float s = 1.0f / c;
    float4 v = pooled[i];
    __half* row = p16 + (size_t)r * 512;
    int c0 = (i - (r << 7)) * 4;
    *(__half2*)(row + c0)     = __halves2half2(__float2half_rn(v.x * s), __float2half_rn(v.y * s));
    *(__half2*)(row + c0 + 2) = __halves2half2(__float2half_rn(v.z * s), __float2half_rn(v.w * s));
}

// ---------------- shared GEMM machinery ---------------------------------------
// CTA 128x128, 4 warps (64x64), BK=64, 2-stage pipeline, 128B-row swizzle.
// R11 layout (verified best): hoisted addresses, full 16-load burst BEFORE
// compute, runtime-K loop. Three alternates (interleave/unroll/prefetch) all
// regressed; this mainloop is frozen.
#define BM 128
#define BN 128
#define BK 64
#define STG 2
#define STG_BYTES 32768

struct AddrCtx {
    uint32_t rbA[4], rbB[4], xoff[4];
};
__device__ __forceinline__ void make_ctx(AddrCtx& cx, int wm, int wn, int lane) {
    #pragma unroll
    for (int mf = 0; mf < 4; mf++) cx.rbA[mf] = (uint32_t)((wm + mf * 16 + (lane & 15)) * 128);
    #pragma unroll
    for (int bi = 0; bi < 4; bi++) cx.rbB[bi] = (uint32_t)((wn + bi * 16 + (lane & 15)) * 128);
    #pragma unroll
    for (int ks = 0; ks < 4; ks++)
        cx.xoff[ks] = (uint32_t)((((ks * 2 + (lane >> 4)) ^ (lane & 7))) << 4);
}

__device__ __forceinline__ void compute_chunk(uint32_t sa, uint32_t sb,
                                              const AddrCtx& cx,
                                              float acc[4][8][4]) {
    #pragma unroll
    for (int ks = 0; ks < 4; ks++) {
        const uint32_t sax = sa + cx.xoff[ks];
        const uint32_t sbx = sb + cx.xoff[ks];
        uint32_t a[4][4], b[8][2];
        #pragma unroll
        for (int mf = 0; mf < 4; mf++)
            ldm_x4(a[mf][0], a[mf][1], a[mf][2], a[mf][3], sax + cx.rbA[mf]);
        #pragma unroll
        for (int bi = 0; bi < 4; bi++) {
            uint32_t r0, r1, r2, r3;
            ldm_x4(r0, r1, r2, r3, sbx + cx.rbB[bi]);
            b[bi*2+0][0] = r0; b[bi*2+0][1] = r2;
            b[bi*2+1][0] = r1; b[bi*2+1][1] = r3;
        }
        #pragma unroll
        for (int mf = 0; mf < 4; mf++)
            #pragma unroll
            for (int nf = 0; nf < 8; nf++)
                mma_f16(acc[mf][nf], a[mf], b[nf]);
    }
}

// ---------------- GEMM1 with fused edge gather --------------------------------
__global__ void __launch_bounds__(128, 3)
g1_gemm(const __half* __restrict__ objh, const __half* __restrict__ predh,
        const int* __restrict__ edges, const __half* __restrict__ Bt,
        const float* __restrict__ bias, __half* __restrict__ outh)
{
    extern __shared__ char smem[];
    const int tid  = threadIdx.x;
    const int wid  = tid >> 5;
    const int lane = tid & 31;
    const int m0   = blockIdx.y * BM;
    const int n0   = blockIdx.x * BN;
    const int wm   = (wid >> 1) * 64;
    const int wn   = (wid & 1) * 64;
    const int M    = T_N;
    const int Kc   = 384;
    const uint32_t sbase = smem_u32(smem);

    int2* esm = (int2*)(smem + STG * STG_BYTES);
    {
        int gr = m0 + tid;
        esm[tid] = (gr < M) ? *(const int2*)&edges[2*gr] : make_int2(0, 0);
    }
    __syncthreads();

    AddrCtx cx; make_ctx(cx, wm, wn, lane);
    const int lrow = tid >> 3, lch = tid & 7;
    const uint32_t off0 = (uint32_t)(lrow * 128 + ((lch ^ (lrow & 7)) << 4));
    const __half* bBase = Bt + (size_t)(n0 + lrow) * Kc + lch * 8;

    float acc[4][8][4];
    #pragma unroll
    for (int i = 0; i < 4; i++)
        #pragma unroll
        for (int j = 0; j < 8; j++)
            #pragma unroll
            for (int k = 0; k < 4; k++) acc[i][j][k] = 0.f;

    auto ld_tile = [&](int it, int buf) {
        const int kp  = it * BK;
        const int reg = kp >> 7;          // 0: obj[s], 1: pred, 2: obj[o]
        const int kc  = (kp & 127) + lch * 8;
        uint32_t sa = sbase + buf * STG_BYTES;
        uint32_t sb = sa + 16384;
        #pragma unroll
        for (int t = 0; t < 8; t++) {
            int row = lrow + t * 16;
            const __half* src;
            if (reg == 0)      src = objh  + (size_t)esm[row].x * DIN + kc;
            else if (reg == 1) src = predh + (size_t)(m0 + row) * DIN + kc;
            else               src = objh  + (size_t)esm[row].y * DIN + kc;
            cp_async16(sa + off0 + t * 2048, src);
        }
        const __half* pb = bBase + kp;
        #pragma unroll
        for (int t = 0; t < 8; t++) {
            cp_async16(sb + off0 + t * 2048, pb);
            pb += 16 * Kc;
        }
    };

    const int NC = Kc / BK;   // 6
    ld_tile(0, 0);
    asm volatile("cp.async.commit_group;" ::: "memory");
    for (int it = 0; it < NC; it++) {
        asm volatile("cp.async.wait_group 0;" ::: "memory");
        __syncthreads();
        if (it + 1 < NC) ld_tile(it + 1, (it + 1) & 1);
        asm volatile("cp.async.commit_group;" ::: "memory");
        uint32_t sa = sbase + (it & 1) * STG_BYTES;
        compute_chunk(sa, sa + 16384, cx, acc);
    }

    float bc[8][2];
    #pragma unroll
    for (int nf = 0; nf < 8; nf++) {
        float2 bv = __ldg((const float2*)&bias[n0 + wn + nf * 8 + (lane & 3) * 2]);
        bc[nf][0] = bv.x; bc[nf][1] = bv.y;
    }
    #pragma unroll
    for (int mf = 0; mf < 4; mf++)
        #pragma unroll
        for (int rh = 0; rh < 2; rh++) {
            const int gr = m0 + wm + mf * 16 + (lane >> 2) + rh * 8;
            if (gr >= M) continue;
            #pragma unroll
            for (int nf = 0; nf < 8; nf++) {
                const int col = n0 + wn + nf * 8 + (lane & 3) * 2;
                float v0 = fmaxf(acc[mf][nf][rh*2+0] + bc[nf][0], 0.f);
                float v1 = fmaxf(acc[mf][nf][rh*2+1] + bc[nf][1], 0.f);
                *(__half2*)&outh[(size_t)gr * HID + col] =
                    __halves2half2(__float2half_rn(v0), __float2half_rn(v1));
            }
        }
}

// ---------------- generic GEMM -------------------------------------------------
// A padded beyond M (garbage rows discarded by guarded epilogue).
// EPI 0: fp32 store    EPI 2: GEMM2 router    EPI 3: plain fp16 store
template<int EPI>
__global__ void __launch_bounds__(128, 3)
mma_gemm(const __half* __restrict__ A, const __half* __restrict__ Bt,
         const float* __restrict__ bias, float* __restrict__ outf,
         __half* __restrict__ outh,
         int M, int strideA, int Kc, int ostride,
         const int* __restrict__ edges, float* __restrict__ pooled,
         float* __restrict__ newp)
{
    extern __shared__ char smem[];
    const int tid  = threadIdx.x;
    const int wid  = tid >> 5;
    const int lane = tid & 31;
    const int m0   = blockIdx.y * BM;
    const int n0   = blockIdx.x * BN;
    const int wm   = (wid >> 1) * 64;
    const int wn   = (wid & 1) * 64;
    const uint32_t sbase = smem_u32(smem);

    AddrCtx cx; make_ctx(cx, wm, wn, lane);
    const int lrow = tid >> 3, lch = tid & 7;
    const uint32_t off0 = (uint32_t)(lrow * 128 + ((lch ^ (lrow & 7)) << 4));
    const __half* aBase = A  + (size_t)(m0 + lrow) * strideA + lch * 8;
    const __half* bBase = Bt + (size_t)(n0 + lrow) * Kc      + lch * 8;

    float acc[4][8][4];
    #pragma unroll
    for (int i = 0; i < 4; i++)
        #pragma unroll
        for (int j = 0; j < 8; j++)
            #pragma unroll
            for (int k = 0; k < 4; k++) acc[i][j][k] = 0.f;

    auto ld_tile = [&](int it, int buf) {
        const int kp = it * BK;
        uint32_t sa = sbase + buf * STG_BYTES;
        uint32_t sb = sa + 16384;
        const __half* pa = aBase + kp;
        const __half* pb = bBase + kp;
        #pragma unroll
        for (int t = 0; t < 8; t++) {
            cp_async16(sa + off0 + t * 2048, pa);
            pa += 16 * strideA;
        }
        #pragma unroll
        for (int t = 0; t < 8; t++) {
            cp_async16(sb + off0 + t * 2048, pb);
            pb += 16 * Kc;
        }
    };

    const int NC = Kc / BK;
    ld_tile(0, 0);
    asm volatile("cp.async.commit_group;" ::: "memory");
    for (int it = 0; it < NC; it++) {
        asm volatile("cp.async.wait_group 0;" ::: "memory");
        __syncthreads();
        if (it + 1 < NC) ld_tile(it + 1, (it + 1) & 1);
        asm volatile("cp.async.commit_group;" ::: "memory");
        uint32_t sa = sbase + (it & 1) * STG_BYTES;
        compute_chunk(sa, sa + 16384, cx, acc);
    }

    float bc[8][2];
    #pragma unroll
    for (int nf = 0; nf < 8; nf++) {
        float2 bv = __ldg((const float2*)&bias[n0 + wn + nf * 8 + (lane & 3) * 2]);
        bc[nf][0] = bv.x; bc[nf][1] = bv.y;
    }

    #pragma unroll
    for (int mf = 0; mf < 4; mf++)
        #pragma unroll
        for (int rh = 0; rh < 2; rh++) {
            const int gr = m0 + wm + mf * 16 + (lane >> 2) + rh * 8;
            if (gr >= M) continue;
            int es = 0, eo = 0;
            if (EPI == 2) {
                int2 e = *(const int2*)&edges[2*gr];
                es = e.x; eo = e.y;
            }
            #pragma unroll
            for (int nf = 0; nf < 8; nf++) {
                const int col = n0 + wn + nf * 8 + (lane & 3) * 2;
                float v0 = fmaxf(acc[mf][nf][rh*2+0] + bc[nf][0], 0.f);
                float v1 = fmaxf(acc[mf][nf][rh*2+1] + bc[nf][1], 0.f);
                if (EPI == 0) {
                    *(float2*)&outf[(size_t)gr * ostride + col] = make_float2(v0, v1);
                } else if (EPI == 3) {
                    *(__half2*)&outh[(size_t)gr * ostride + col] =
                        __halves2half2(__float2half_rn(v0), __float2half_rn(v1));
                } else {
                    if (col < HID) {
                        red_add2(&pooled[(size_t)es * HID + col], v0, v1);
                    } else if (col < HID + DOUT) {
                        *(float2*)&newp[(size_t)gr * DOUT + (col - HID)] = make_float2(v0, v1);
                    } else {
                        red_add2(&pooled[(size_t)eo * HID + (col - HID - DOUT)], v0, v1);
                    }
                }
            }
        }
}

// ---------------- launch ------------------------------------------------------
// 7 launches; GEMM2 is launch #4 (the profiled slot).
extern "C" void kernel_launch(void* const* d_in, const int* in_sizes, int n_in,
                              void* d_out, int out_size) {
    const float* obj  = (const float*)d_in[0];
    const float* pred = (const float*)d_in[1];
    const int*   edges= (const int*)  d_in[2];
    const float* W1a  = (const float*)d_in[3];
    const float* b1a  = (const float*)d_in[4];
    const float* W1b  = (const float*)d_in[5];
    const float* b1b  = (const float*)d_in[6];
    const float* W2a  = (const float*)d_in[7];
    const float* b2a  = (const float*)d_in[8];
    const float* W2b  = (const float*)d_in[9];
    const float* b2b  = (const float*)d_in[10];

    float* out     = (float*)d_out;
    float* new_obj = out;                       // [O, 128]
    float* new_p   = out + (size_t)O_N * DOUT;  // [T, 128]

    __half *objh, *predh, *h16, *p16, *h2, *bt1, *bt2, *bt3, *bt4;
    float *pooled, *cnt;
    cudaGetSymbolAddress((void**)&objh,   g_objh);
    cudaGetSymbolAddress((void**)&predh,  g_predh);
    cudaGetSymbolAddress((void**)&h16,    g_h);
    cudaGetSymbolAddress((void**)&pooled, g_pool);
    cudaGetSymbolAddress((void**)&p16,    g_pool16);
    cudaGetSymbolAddress((void**)&h2,     g_h2);
    cudaGetSymbolAddress((void**)&cnt,    g_cnt);
    cudaGetSymbolAddress((void**)&bt1,    g_bt1);
    cudaGetSymbolAddress((void**)&bt2,    g_bt2);
    cudaGetSymbolAddress((void**)&bt3,    g_bt3);
    cudaGetSymbolAddress((void**)&bt4,    g_bt4);

    const int SMEM_G  = STG * STG_BYTES;          // 65536
    const int SMEM_G1 = SMEM_G + 128 * 8;         // + edge cache (1 KB)
    cudaFuncSetAttribute((const void*)g1_gemm,     cudaFuncAttributeMaxDynamicSharedMemorySize, SMEM_G1);
    cudaFuncSetAttribute((const void*)mma_gemm<0>, cudaFuncAttributeMaxDynamicSharedMemorySize, SMEM_G);
    cudaFuncSetAttribute((const void*)mma_gemm<2>, cudaFuncAttributeMaxDynamicSharedMemorySize, SMEM_G);
    cudaFuncSetAttribute((const void*)mma_gemm<3>, cudaFuncAttributeMaxDynamicSharedMemorySize, SMEM_G);

    const int MT_T = (T_N + 127) / 128;   // 1563
    const int MT_O = (O_N + 127) / 128;   // 391

    // 1: zero pooled/cnt + obj/pred fp16 converts
    {   int span = T_N * DIN / 4;   // 6.4M
        prep1<<<(span + 255) / 256, 256>>>(
            (const float4*)obj, (__half2*)objh,
            (const float4*)pred, (__half2*)predh,
            (float4*)pooled, cnt); }

    // 2: all weight transposes + degree counts
    prep2<<<(1114112 + 255) / 256, 256>>>(W1a, W1b, W2a, W2b,
                                          bt1, bt2, bt3, bt4, edges, cnt);

    // 3: GEMM1 (fused gather)
    g1_gemm<<<dim3(4, MT_T), 128, SMEM_G1>>>(objh, predh, edges, bt1, b1a, h16);

    // 4: GEMM2 (scatter s/o + new_p)   <-- profiled slot
    mma_gemm<2><<<dim3(9, MT_T), 128, SMEM_G>>>(
        h16, bt2, b1b, nullptr, nullptr,
        T_N, 512, 512, 0, edges, pooled, new_p);

    // 5: pooled scale + fp16
    pscale_conv<<<(O_N * (HID / 4) + 255) / 256, 256>>>((const float4*)pooled, cnt, p16);

    // 6: GEMM3
    mma_gemm<3><<<dim3(4, MT_O), 128, SMEM_G>>>(
        p16, bt3, b2a, nullptr, h2,
        O_N, 512, 512, HID, nullptr, nullptr, nullptr);

    // 7: GEMM4
    mma_gemm<0><<<dim3(1, MT_O), 128, SMEM_G>>>(
        h2, bt4, b2b, new_obj, nullptr,
        O_N, 512, 512, DOUT, nullptr, nullptr, nullptr);
}

// round 16
// speedup vs baseline: 1.1438x; 1.0002x over previous
#include <cuda_runtime.h>
#include <cuda_fp16.h>
#include <cstdint>

#define O_N   50000
#define T_N   200000
#define DIN   128
#define HID   512
#define DOUT  128

// padded row counts (one extra M-tile so GEMM loaders need no bounds checks)
#define T_PAD 200064
#define O_PAD 50048

// ---------------- device scratch (allocation-free rule) -----------------------
__device__ __half  g_objh [(size_t)O_N * DIN];    // obj fp16 (indexed, no pad needed)
__device__ __half  g_predh[(size_t)T_PAD * DIN];  // pred fp16 (padded)
__device__ __half  g_h    [(size_t)T_PAD * 512];  // [T, 512] fp16 (padded)
__device__ float   g_pool [(size_t)O_N * HID];    // fp32 accum
__device__ __half  g_pool16[(size_t)O_PAD * 512]; // pooled fp16 (padded)
__device__ __half  g_h2   [(size_t)O_PAD * 512];  // [O, 512] fp16 (padded)
__device__ float   g_cnt  [O_N];
__device__ __half  g_bt1[(size_t)512  * 384];     // [N,K] fp16 (W1a^T)
__device__ __half  g_bt2[(size_t)1152 * 512];     // [N,K] fp16 (W1b^T)
__device__ __half  g_bt3[(size_t)512  * 512];     // [N,K] fp16 (W2a^T)
__device__ __half  g_bt4[(size_t)128  * 512];     // [N,K] fp16 (W2b^T)

// ---------------- PTX helpers -------------------------------------------------
__device__ __forceinline__ uint32_t smem_u32(const void* p) {
    uint32_t a;
    asm("{ .reg .u64 t; cvta.to.shared.u64 t, %1; cvt.u32.u64 %0, t; }" : "=r"(a) : "l"(p));
    return a;
}
__device__ __forceinline__ void cp_async16(uint32_t dst, const void* src) {
    asm volatile("cp.async.cg.shared.global [%0], [%1], 16;"
                 :: "r"(dst), "l"(src));
}
__device__ __forceinline__ void ldm_x4(uint32_t& r0, uint32_t& r1, uint32_t& r2,
                                       uint32_t& r3, uint32_t addr) {
    asm volatile("ldmatrix.sync.aligned.m8n8.x4.shared.b16 {%0,%1,%2,%3}, [%4];"
                 : "=r"(r0), "=r"(r1), "=r"(r2), "=r"(r3) : "r"(addr));
}
__device__ __forceinline__ void mma_f16(float* c, const uint32_t* a, const uint32_t* b) {
    asm volatile("mma.sync.aligned.m16n8k16.row.col.f32.f16.f16.f32 "
                 "{%0,%1,%2,%3}, {%4,%5,%6,%7}, {%8,%9}, {%0,%1,%2,%3};"
                 : "+f"(c[0]), "+f"(c[1]), "+f"(c[2]), "+f"(c[3])
                 : "r"(a[0]), "r"(a[1]), "r"(a[2]), "r"(a[3]), "r"(b[0]), "r"(b[1]));
}
__device__ __forceinline__ void red_add2(float* p, float a, float b) {
    asm volatile("red.global.add.v2.f32 [%0], {%1,%2};"
                 :: "l"(p), "f"(a), "f"(b) : "memory");
}
// streaming (evict-first) stores for write-once data
__device__ __forceinline__ void st_cs_u32(void* p, uint32_t v) {
    asm volatile("st.global.cs.b32 [%0], %1;" :: "l"(p), "r"(v) : "memory");
}
__device__ __forceinline__ void st_cs_f2(void* p, float a, float b) {
    asm volatile("st.global.cs.v2.f32 [%0], {%1,%2};" :: "l"(p), "f"(a), "f"(b) : "memory");
}

// ---------------- prep 1: zero pooled/cnt + obj/pred fp32->fp16 ----------------
__global__ void prep1(const float4* __restrict__ obj, __half2* __restrict__ objh,
                      const float4* __restrict__ pred, __half2* __restrict__ predh,
                      float4* __restrict__ pool4, float* __restrict__ cnt) {
    int i = blockIdx.x * 256 + threadIdx.x;
    const int n4_obj  = O_N * DIN / 4;
    const int n4_pred = T_N * DIN / 4;
    const int n4_pool = O_N * HID / 4;
    if (i < n4_pool) pool4[i] = make_float4(0.f, 0.f, 0.f, 0.f);
    if (i < O_N) cnt[i] = 0.f;
    if (i < n4_obj) {
        float4 v = obj[i];
        objh[2*i]   = __halves2half2(__float2half_rn(v.x), __float2half_rn(v.y));
        objh[2*i+1] = __halves2half2(__float2half_rn(v.z), __float2half_rn(v.w));
    }
    if (i < n4_pred) {
        float4 v = pred[i];
        predh[2*i]   = __halves2half2(__float2half_rn(v.x), __float2half_rn(v.y));
        predh[2*i+1] = __halves2half2(__float2half_rn(v.z), __float2half_rn(v.w));
    }
}

// ---------------- prep 2: all weight transposes + degree counts ----------------
__global__ void prep2(const float* __restrict__ W1a, const float* __restrict__ W1b,
                      const float* __restrict__ W2a, const float* __restrict__ W2b,
                      __half* __restrict__ bt1, __half* __restrict__ bt2,
                      __half* __restrict__ bt3, __half* __restrict__ bt4,
                      const int* __restrict__ edges, float* __restrict__ cnt) {
    int i = blockIdx.x * 256 + threadIdx.x;
    if (i < T_N) {
        atomicAdd(&cnt[edges[2*i]], 1.0f);
        atomicAdd(&cnt[edges[2*i + 1]], 1.0f);
    }
    const float* W; __half* Bt; int K, N, idx;
    if (i < 196608)       { W = W1a; Bt = bt1; K = 384; N = 512;  idx = i; }
    else if (i < 786432)  { W = W1b; Bt = bt2; K = 512; N = 1152; idx = i - 196608; }
    else if (i < 1048576) { W = W2a; Bt = bt3; K = 512; N = 512;  idx = i - 786432; }
    else if (i < 1114112) { W = W2b; Bt = bt4; K = 512; N = 128;  idx = i - 1048576; }
    else return;
    int n = idx / K, k = idx - n * K;
    Bt[idx] = __float2half_rn(W[(size_t)k * N + n]);
}

// pooled/counts -> plain fp16
__global__ void pscale_conv(const float4* __restrict__ pooled, const float* __restrict__ cnt,
                            __half* __restrict__ p16) {
    int i = blockIdx.x * 256 + threadIdx.x;
    if (i >= O_N * (HID / 4)) return;
    int r = i >> 7;
    float c = fminf(fmaxf(cnt[r], 1.0f), 50000.0f);
    float s = 1.0f / c;
    float4 v = pooled[i];
    __half* row = p16 + (size_t)r * 512;
    int c0 = (i - (r << 7)) * 4;
    *(__half2*)(row + c0)     = __halves2half2(__float2half_rn(v.x * s), __float2half_rn(v.y * s));
    *(__half2*)(row + c0 + 2) = __halves2half2(__float2half_rn(v.z * s), __float2half_rn(v.w * s));
}

// ---------------- shared GEMM machinery ---------------------------------------
// CTA 128x128, 4 warps (64x64), BK=64, 2-stage pipeline, 128B-row swizzle.
// R11 layout (verified best): hoisted addresses, full 16-load burst BEFORE
// compute, runtime-K loop. Mainloop is FROZEN (interleave/unroll/prefetch all
// regressed).
#define BM 128
#define BN 128
#define BK 64
#define STG 2
#define STG_BYTES 32768

struct AddrCtx {
    uint32_t rbA[4], rbB[4], xoff[4];
};
__device__ __forceinline__ void make_ctx(AddrCtx& cx, int wm, int wn, int lane) {
    #pragma unroll
    for (int mf = 0; mf < 4; mf++) cx.rbA[mf] = (uint32_t)((wm + mf * 16 + (lane & 15)) * 128);
    #pragma unroll
    for (int bi = 0; bi < 4; bi++) cx.rbB[bi] = (uint32_t)((wn + bi * 16 + (lane & 15)) * 128);
    #pragma unroll
    for (int ks = 0; ks < 4; ks++)
        cx.xoff[ks] = (uint32_t)((((ks * 2 + (lane >> 4)) ^ (lane & 7))) << 4);
}

__device__ __forceinline__ void compute_chunk(uint32_t sa, uint32_t sb,
                                              const AddrCtx& cx,
                                              float acc[4][8][4]) {
    #pragma unroll
    for (int ks = 0; ks < 4; ks++) {
        const uint32_t sax = sa + cx.xoff[ks];
        const uint32_t sbx = sb + cx.xoff[ks];
        uint32_t a[4][4], b[8][2];
        #pragma unroll
        for (int mf = 0; mf < 4; mf++)
            ldm_x4(a[mf][0], a[mf][1], a[mf][2], a[mf][3], sax + cx.rbA[mf]);
        #pragma unroll
        for (int bi = 0; bi < 4; bi++) {
            uint32_t r0, r1, r2, r3;
            ldm_x4(r0, r1, r2, r3, sbx + cx.rbB[bi]);
            b[bi*2+0][0] = r0; b[bi*2+0][1] = r2;
            b[bi*2+1][0] = r1; b[bi*2+1][1] = r3;
        }
        #pragma unroll
        for (int mf = 0; mf < 4; mf++)
            #pragma unroll
            for (int nf = 0; nf < 8; nf++)
                mma_f16(acc[mf][nf], a[mf], b[nf]);
    }
}

// ---------------- GEMM1 with fused edge gather --------------------------------
__global__ void __launch_bounds__(128, 3)
g1_gemm(const __half* __restrict__ objh, const __half* __restrict__ predh,
        const int* __restrict__ edges, const __half* __restrict__ Bt,
        const float* __restrict__ bias, __half* __restrict__ outh)
{
    extern __shared__ char smem[];
    const int tid  = threadIdx.x;
    const int wid  = tid >> 5;
    const int lane = tid & 31;
    const int m0   = blockIdx.y * BM;
    const int n0   = blockIdx.x * BN;
    const int wm   = (wid >> 1) * 64;
    const int wn   = (wid & 1) * 64;
    const int M    = T_N;
    const int Kc   = 384;
    const uint32_t sbase = smem_u32(smem);

    int2* esm = (int2*)(smem + STG * STG_BYTES);
    {
        int gr = m0 + tid;
        esm[tid] = (gr < M) ? *(const int2*)&edges[2*gr] : make_int2(0, 0);
    }
    __syncthreads();

    AddrCtx cx; make_ctx(cx, wm, wn, lane);
    const int lrow = tid >> 3, lch = tid & 7;
    const uint32_t off0 = (uint32_t)(lrow * 128 + ((lch ^ (lrow & 7)) << 4));
    const __half* bBase = Bt + (size_t)(n0 + lrow) * Kc + lch * 8;

    float acc[4][8][4];
    #pragma unroll
    for (int i = 0; i < 4; i++)
        #pragma unroll
        for (int j = 0; j < 8; j++)
            #pragma unroll
            for (int k = 0; k < 4; k++) acc[i][j][k] = 0.f;

    auto ld_tile = [&](int it, int buf) {
        const int kp  = it * BK;
        const int reg = kp >> 7;          // 0: obj[s], 1: pred, 2: obj[o]
        const int kc  = (kp & 127) + lch * 8;
        uint32_t sa = sbase + buf * STG_BYTES;
        uint32_t sb = sa + 16384;
        #pragma unroll
        for (int t = 0; t < 8; t++) {
            int row = lrow + t * 16;
            const __half* src;
            if (reg == 0)      src = objh  + (size_t)esm[row].x * DIN + kc;
            else if (reg == 1) src = predh + (size_t)(m0 + row) * DIN + kc;
            else               src = objh  + (size_t)esm[row].y * DIN + kc;
            cp_async16(sa + off0 + t * 2048, src);
        }
        const __half* pb = bBase + kp;
        #pragma unroll
        for (int t = 0; t < 8; t++) {
            cp_async16(sb + off0 + t * 2048, pb);
            pb += 16 * Kc;
        }
    };

    const int NC = Kc / BK;   // 6
    ld_tile(0, 0);
    asm volatile("cp.async.commit_group;" ::: "memory");
    for (int it = 0; it < NC; it++) {
        asm volatile("cp.async.wait_group 0;" ::: "memory");
        __syncthreads();
        if (it + 1 < NC) ld_tile(it + 1, (it + 1) & 1);
        asm volatile("cp.async.commit_group;" ::: "memory");
        uint32_t sa = sbase + (it & 1) * STG_BYTES;
        compute_chunk(sa, sa + 16384, cx, acc);
    }

    float bc[8][2];
    #pragma unroll
    for (int nf = 0; nf < 8; nf++) {
        float2 bv = __ldg((const float2*)&bias[n0 + wn + nf * 8 + (lane & 3) * 2]);
        bc[nf][0] = bv.x; bc[nf][1] = bv.y;
    }
    #pragma unroll
    for (int mf = 0; mf < 4; mf++)
        #pragma unroll
        for (int rh = 0; rh < 2; rh++) {
            const int gr = m0 + wm + mf * 16 + (lane >> 2) + rh * 8;
            if (gr >= M) continue;
            #pragma unroll
            for (int nf = 0; nf < 8; nf++) {
                const int col = n0 + wn + nf * 8 + (lane & 3) * 2;
                float v0 = fmaxf(acc[mf][nf][rh*2+0] + bc[nf][0], 0.f);
                float v1 = fmaxf(acc[mf][nf][rh*2+1] + bc[nf][1], 0.f);
                __half2 hv = __halves2half2(__float2half_rn(v0), __float2half_rn(v1));
                // streaming store: h16 (205 MB) exceeds L2; don't evict bt1/objh
                st_cs_u32(&outh[(size_t)gr * HID + col], *(uint32_t*)&hv);
            }
        }
}

// ---------------- generic GEMM -------------------------------------------------
// A padded beyond M (garbage rows discarded by guarded epilogue).
// EPI 0: fp32 store (streaming)    EPI 2: GEMM2 router    EPI 3: fp16 store
template<int EPI>
__global__ void __launch_bounds__(128, 3)
mma_gemm(const __half* __restrict__ A, const __half* __restrict__ Bt,
         const float* __restrict__ bias, float* __restrict__ outf,
         __half* __restrict__ outh,
         int M, int strideA, int Kc, int ostride,
         const int* __restrict__ edges, float* __restrict__ pooled,
         float* __restrict__ newp)
{
    extern __shared__ char smem[];
    const int tid  = threadIdx.x;
    const int wid  = tid >> 5;
    const int lane = tid & 31;
    const int m0   = blockIdx.y * BM;
    const int n0   = blockIdx.x * BN;
    const int wm   = (wid >> 1) * 64;
    const int wn   = (wid & 1) * 64;
    const uint32_t sbase = smem_u32(smem);

    AddrCtx cx; make_ctx(cx, wm, wn, lane);
    const int lrow = tid >> 3, lch = tid & 7;
    const uint32_t off0 = (uint32_t)(lrow * 128 + ((lch ^ (lrow & 7)) << 4));
    const __half* aBase = A  + (size_t)(m0 + lrow) * strideA + lch * 8;
    const __half* bBase = Bt + (size_t)(n0 + lrow) * Kc      + lch * 8;

    float acc[4][8][4];
    #pragma unroll
    for (int i = 0; i < 4; i++)
        #pragma unroll
        for (int j = 0; j < 8; j++)
            #pragma unroll
            for (int k = 0; k < 4; k++) acc[i][j][k] = 0.f;

    auto ld_tile = [&](int it, int buf) {
        const int kp = it * BK;
        uint32_t sa = sbase + buf * STG_BYTES;
        uint32_t sb = sa + 16384;
        const __half* pa = aBase + kp;
        const __half* pb = bBase + kp;
        #pragma unroll
        for (int t = 0; t < 8; t++) {
            cp_async16(sa + off0 + t * 2048, pa);
            pa += 16 * strideA;
        }
        #pragma unroll
        for (int t = 0; t < 8; t++) {
            cp_async16(sb + off0 + t * 2048, pb);
            pb += 16 * Kc;
        }
    };

    const int NC = Kc / BK;
    ld_tile(0, 0);
    asm volatile("cp.async.commit_group;" ::: "memory");
    for (int it = 0; it < NC; it++) {
        asm volatile("cp.async.wait_group 0;" ::: "memory");
        __syncthreads();
        if (it + 1 < NC) ld_tile(it + 1, (it + 1) & 1);
        asm volatile("cp.async.commit_group;" ::: "memory");
        uint32_t sa = sbase + (it & 1) * STG_BYTES;
        compute_chunk(sa, sa + 16384, cx, acc);
    }

    float bc[8][2];
    #pragma unroll
    for (int nf = 0; nf < 8; nf++) {
        float2 bv = __ldg((const float2*)&bias[n0 + wn + nf * 8 + (lane & 3) * 2]);
        bc[nf][0] = bv.x; bc[nf][1] = bv.y;
    }

    #pragma unroll
    for (int mf = 0; mf < 4; mf++)
        #pragma unroll
        for (int rh = 0; rh < 2; rh++) {
            const int gr = m0 + wm + mf * 16 + (lane >> 2) + rh * 8;
            if (gr >= M) continue;
            int es = 0, eo = 0;
            if (EPI == 2) {
                int2 e = *(const int2*)&edges[2*gr];
                es = e.x; eo = e.y;
            }
            #pragma unroll
            for (int nf = 0; nf < 8; nf++) {
                const int col = n0 + wn + nf * 8 + (lane & 3) * 2;
                float v0 = fmaxf(acc[mf][nf][rh*2+0] + bc[nf][0], 0.f);
                float v1 = fmaxf(acc[mf][nf][rh*2+1] + bc[nf][1], 0.f);
                if (EPI == 0) {
                    // new_obj: final output, never re-read -> streaming
                    st_cs_f2(&outf[(size_t)gr * ostride + col], v0, v1);
                } else if (EPI == 3) {
                    // h2: re-read by GEMM4 immediately (51 MB, L2-fits) -> normal
                    *(__half2*)&outh[(size_t)gr * ostride + col] =
                        __halves2half2(__float2half_rn(v0), __float2half_rn(v1));
                } else {
                    if (col < HID) {
                        red_add2(&pooled[(size_t)es * HID + col], v0, v1);
                    } else if (col < HID + DOUT) {
                        // new_p: final output, never re-read -> streaming
                        st_cs_f2(&newp[(size_t)gr * DOUT + (col - HID)], v0, v1);
                    } else {
                        red_add2(&pooled[(size_t)eo * HID + (col - HID - DOUT)], v0, v1);
                    }
                }
            }
        }
}

// ---------------- launch ------------------------------------------------------
// 7 launches; GEMM2 is launch #4 (the profiled slot).
extern "C" void kernel_launch(void* const* d_in, const int* in_sizes, int n_in,
                              void* d_out, int out_size) {
    const float* obj  = (const float*)d_in[0];
    const float* pred = (const float*)d_in[1];
    const int*   edges= (const int*)  d_in[2];
    const float* W1a  = (const float*)d_in[3];
    const float* b1a  = (const float*)d_in[4];
    const float* W1b  = (const float*)d_in[5];
    const float* b1b  = (const float*)d_in[6];
    const float* W2a  = (const float*)d_in[7];
    const float* b2a  = (const float*)d_in[8];
    const float* W2b  = (const float*)d_in[9];
    const float* b2b  = (const float*)d_in[10];

    float* out     = (float*)d_out;
    float* new_obj = out;                       // [O, 128]
    float* new_p   = out + (size_t)O_N * DOUT;  // [T, 128]

    __half *objh, *predh, *h16, *p16, *h2, *bt1, *bt2, *bt3, *bt4;
    float *pooled, *cnt;
    cudaGetSymbolAddress((void**)&objh,   g_objh);
    cudaGetSymbolAddress((void**)&predh,  g_predh);
    cudaGetSymbolAddress((void**)&h16,    g_h);
    cudaGetSymbolAddress((void**)&pooled, g_pool);
    cudaGetSymbolAddress((void**)&p16,    g_pool16);
    cudaGetSymbolAddress((void**)&h2,     g_h2);
    cudaGetSymbolAddress((void**)&cnt,    g_cnt);
    cudaGetSymbolAddress((void**)&bt1,    g_bt1);
    cudaGetSymbolAddress((void**)&bt2,    g_bt2);
    cudaGetSymbolAddress((void**)&bt3,    g_bt3);
    cudaGetSymbolAddress((void**)&bt4,    g_bt4);

    const int SMEM_G  = STG * STG_BYTES;          // 65536
    const int SMEM_G1 = SMEM_G + 128 * 8;         // + edge cache (1 KB)
    cudaFuncSetAttribute((const void*)g1_gemm,     cudaFuncAttributeMaxDynamicSharedMemorySize, SMEM_G1);
    cudaFuncSetAttribute((const void*)mma_gemm<0>, cudaFuncAttributeMaxDynamicSharedMemorySize, SMEM_G);
    cudaFuncSetAttribute((const void*)mma_gemm<2>, cudaFuncAttributeMaxDynamicSharedMemorySize, SMEM_G);
    cudaFuncSetAttribute((const void*)mma_gemm<3>, cudaFuncAttributeMaxDynamicSharedMemorySize, SMEM_G);

    const int MT_T = (T_N + 127) / 128;   // 1563
    const int MT_O = (O_N + 127) / 128;   // 391

    // 1: zero pooled/cnt + obj/pred fp16 converts
    {   int span = T_N * DIN / 4;   // 6.4M
        prep1<<<(span + 255) / 256, 256>>>(
            (const float4*)obj, (__half2*)objh,
            (const float4*)pred, (__half2*)predh,
            (float4*)pooled, cnt); }

    // 2: all weight transposes + degree counts
    prep2<<<(1114112 + 255) / 256, 256>>>(W1a, W1b, W2a, W2b,
                                          bt1, bt2, bt3, bt4, edges, cnt);

    // 3: GEMM1 (fused gather)
    g1_gemm<<<dim3(4, MT_T), 128, SMEM_G1>>>(objh, predh, edges, bt1, b1a, h16);

    // 4: GEMM2 (scatter s/o + new_p)   <-- profiled slot
    mma_gemm<2><<<dim3(9, MT_T), 128, SMEM_G>>>(
        h16, bt2, b1b, nullptr, nullptr,
        T_N, 512, 512, 0, edges, pooled, new_p);

    // 5: pooled scale + fp16
    pscale_conv<<<(O_N * (HID / 4) + 255) / 256, 256>>>((const float4*)pooled, cnt, p16);

    // 6: GEMM3
    mma_gemm<3><<<dim3(4, MT_O), 128, SMEM_G>>>(
        p16, bt3, b2a, nullptr, h2,
        O_N, 512, 512, HID, nullptr, nullptr, nullptr);

    // 7: GEMM4
    mma_gemm<0><<<dim3(1, MT_O), 128, SMEM_G>>>(
        h2, bt4, b2b, new_obj, nullptr,
        O_N, 512, 512, DOUT, nullptr, nullptr, nullptr);
}

// round 17
// speedup vs baseline: 1.1456x; 1.0016x over previous
#include <cuda_runtime.h>
#include <cuda_fp16.h>
#include <cstdint>

#define O_N   50000
#define T_N   200000
#define DIN   128
#define HID   512
#define DOUT  128

// padded row counts (one extra M-tile so GEMM loaders need no bounds checks)
#define T_PAD 200064
#define O_PAD 50048

// ---------------- device scratch (allocation-free rule) -----------------------
__device__ __half  g_objh [(size_t)O_N * DIN];    // obj fp16 (indexed, no pad needed)
__device__ __half  g_predh[(size_t)T_PAD * DIN];  // pred fp16 (padded)
__device__ __half  g_h    [(size_t)T_PAD * 512];  // [T, 512] fp16 (padded)
__device__ float   g_pool [(size_t)O_N * HID];    // fp32 accum
__device__ __half  g_pool16[(size_t)O_PAD * 512]; // pooled fp16 (padded)
__device__ __half  g_h2   [(size_t)O_PAD * 512];  // [O, 512] fp16 (padded)
__device__ float   g_cnt  [O_N];
__device__ __half  g_bt1[(size_t)512  * 384];     // [N,K] fp16 (W1a^T)
__device__ __half  g_bt2[(size_t)1152 * 512];     // [N,K] fp16 (W1b^T)
__device__ __half  g_bt3[(size_t)512  * 512];     // [N,K] fp16 (W2a^T)
__device__ __half  g_bt4[(size_t)128  * 512];     // [N,K] fp16 (W2b^T)

// ---------------- PTX helpers -------------------------------------------------
__device__ __forceinline__ uint32_t smem_u32(const void* p) {
    uint32_t a;
    asm("{ .reg .u64 t; cvta.to.shared.u64 t, %1; cvt.u32.u64 %0, t; }" : "=r"(a) : "l"(p));
    return a;
}
__device__ __forceinline__ void cp_async16(uint32_t dst, const void* src) {
    asm volatile("cp.async.cg.shared.global [%0], [%1], 16;"
                 :: "r"(dst), "l"(src));
}
__device__ __forceinline__ void ldm_x4(uint32_t& r0, uint32_t& r1, uint32_t& r2,
                                       uint32_t& r3, uint32_t addr) {
    asm volatile("ldmatrix.sync.aligned.m8n8.x4.shared.b16 {%0,%1,%2,%3}, [%4];"
                 : "=r"(r0), "=r"(r1), "=r"(r2), "=r"(r3) : "r"(addr));
}
__device__ __forceinline__ void mma_f16(float* c, const uint32_t* a, const uint32_t* b) {
    asm volatile("mma.sync.aligned.m16n8k16.row.col.f32.f16.f16.f32 "
                 "{%0,%1,%2,%3}, {%4,%5,%6,%7}, {%8,%9}, {%0,%1,%2,%3};"
                 : "+f"(c[0]), "+f"(c[1]), "+f"(c[2]), "+f"(c[3])
                 : "r"(a[0]), "r"(a[1]), "r"(a[2]), "r"(a[3]), "r"(b[0]), "r"(b[1]));
}
__device__ __forceinline__ void red_add2(float* p, float a, float b) {
    asm volatile("red.global.add.v2.f32 [%0], {%1,%2};"
                 :: "l"(p), "f"(a), "f"(b) : "memory");
}
// streaming (evict-first) stores for write-once data
__device__ __forceinline__ void st_cs_u32(void* p, uint32_t v) {
    asm volatile("st.global.cs.b32 [%0], %1;" :: "l"(p), "r"(v) : "memory");
}
__device__ __forceinline__ void st_cs_f2(void* p, float a, float b) {
    asm volatile("st.global.cs.v2.f32 [%0], {%1,%2};" :: "l"(p), "f"(a), "f"(b) : "memory");
}

// ---------------- merged prep: zero pooled + converts + weights + counts -------
// cnt is pre-zeroed by a stream-ordered cudaMemsetAsync (launch #1), so the
// counts atomics here have no ordering hazard. One grid covers all index spaces.
__global__ void prep_all(const float4* __restrict__ obj, __half2* __restrict__ objh,
                         const float4* __restrict__ pred, __half2* __restrict__ predh,
                         float4* __restrict__ pool4,
                         const float* __restrict__ W1a, const float* __restrict__ W1b,
                         const float* __restrict__ W2a, const float* __restrict__ W2b,
                         __half* __restrict__ bt1, __half* __restrict__ bt2,
                         __half* __restrict__ bt3, __half* __restrict__ bt4,
                         const int* __restrict__ edges, float* __restrict__ cnt) {
    int i = blockIdx.x * 256 + threadIdx.x;
    const int n4_obj  = O_N * DIN / 4;   // 1.6M
    const int n4_pred = T_N * DIN / 4;   // 6.4M
    const int n4_pool = O_N * HID / 4;   // 6.4M
    if (i < n4_pool) pool4[i] = make_float4(0.f, 0.f, 0.f, 0.f);
    if (i < n4_obj) {
        float4 v = obj[i];
        objh[2*i]   = __halves2half2(__float2half_rn(v.x), __float2half_rn(v.y));
        objh[2*i+1] = __halves2half2(__float2half_rn(v.z), __float2half_rn(v.w));
    }
    if (i < n4_pred) {
        float4 v = pred[i];
        predh[2*i]   = __halves2half2(__float2half_rn(v.x), __float2half_rn(v.y));
        predh[2*i+1] = __halves2half2(__float2half_rn(v.z), __float2half_rn(v.w));
    }
    if (i < T_N) {
        atomicAdd(&cnt[edges[2*i]], 1.0f);
        atomicAdd(&cnt[edges[2*i + 1]], 1.0f);
    }
    // weight transposes: bt1 196608 | bt2 589824 | bt3 262144 | bt4 65536
    const float* W; __half* Bt; int K, N, idx;
    if (i < 196608)       { W = W1a; Bt = bt1; K = 384; N = 512;  idx = i; }
    else if (i < 786432)  { W = W1b; Bt = bt2; K = 512; N = 1152; idx = i - 196608; }
    else if (i < 1048576) { W = W2a; Bt = bt3; K = 512; N = 512;  idx = i - 786432; }
    else if (i < 1114112) { W = W2b; Bt = bt4; K = 512; N = 128;  idx = i - 1048576; }
    else return;
    int n = idx / K, k = idx - n * K;
    Bt[idx] = __float2half_rn(W[(size_t)k * N + n]);
}

// pooled/counts -> plain fp16
__global__ void pscale_conv(const float4* __restrict__ pooled, const float* __restrict__ cnt,
                            __half* __restrict__ p16) {
    int i = blockIdx.x * 256 + threadIdx.x;
    if (i >= O_N * (HID / 4)) return;
    int r = i >> 7;
    float c = fminf(fmaxf(cnt[r], 1.0f), 50000.0f);
    float s = 1.0f / c;
    float4 v = pooled[i];
    __half* row = p16 + (size_t)r * 512;
    int c0 = (i - (r << 7)) * 4;
    *(__half2*)(row + c0)     = __halves2half2(__float2half_rn(v.x * s), __float2half_rn(v.y * s));
    *(__half2*)(row + c0 + 2) = __halves2half2(__float2half_rn(v.z * s), __float2half_rn(v.w * s));
}

// ---------------- shared GEMM machinery ---------------------------------------
// CTA 128x128, 4 warps (64x64), BK=64, 2-stage pipeline, 128B-row swizzle.
// R11 layout (verified best): hoisted addresses, full 16-load burst BEFORE
// compute, runtime-K loop. Mainloop is FROZEN.
#define BM 128
#define BN 128
#define BK 64
#define STG 2
#define STG_BYTES 32768

struct AddrCtx {
    uint32_t rbA[4], rbB[4], xoff[4];
};
__device__ __forceinline__ void make_ctx(AddrCtx& cx, int wm, int wn, int lane) {
    #pragma unroll
    for (int mf = 0; mf < 4; mf++) cx.rbA[mf] = (uint32_t)((wm + mf * 16 + (lane & 15)) * 128);
    #pragma unroll
    for (int bi = 0; bi < 4; bi++) cx.rbB[bi] = (uint32_t)((wn + bi * 16 + (lane & 15)) * 128);
    #pragma unroll
    for (int ks = 0; ks < 4; ks++)
        cx.xoff[ks] = (uint32_t)((((ks * 2 + (lane >> 4)) ^ (lane & 7))) << 4);
}

__device__ __forceinline__ void compute_chunk(uint32_t sa, uint32_t sb,
                                              const AddrCtx& cx,
                                              float acc[4][8][4]) {
    #pragma unroll
    for (int ks = 0; ks < 4; ks++) {
        const uint32_t sax = sa + cx.xoff[ks];
        const uint32_t sbx = sb + cx.xoff[ks];
        uint32_t a[4][4], b[8][2];
        #pragma unroll
        for (int mf = 0; mf < 4; mf++)
            ldm_x4(a[mf][0], a[mf][1], a[mf][2], a[mf][3], sax + cx.rbA[mf]);
        #pragma unroll
        for (int bi = 0; bi < 4; bi++) {
            uint32_t r0, r1, r2, r3;
            ldm_x4(r0, r1, r2, r3, sbx + cx.rbB[bi]);
            b[bi*2+0][0] = r0; b[bi*2+0][1] = r2;
            b[bi*2+1][0] = r1; b[bi*2+1][1] = r3;
        }
        #pragma unroll
        for (int mf = 0; mf < 4; mf++)
            #pragma unroll
            for (int nf = 0; nf < 8; nf++)
                mma_f16(acc[mf][nf], a[mf], b[nf]);
    }
}

// ---------------- GEMM1 with fused edge gather --------------------------------
__global__ void __launch_bounds__(128, 3)
g1_gemm(const __half* __restrict__ objh, const __half* __restrict__ predh,
        const int* __restrict__ edges, const __half* __restrict__ Bt,
        const float* __restrict__ bias, __half* __restrict__ outh)
{
    extern __shared__ char smem[];
    const int tid  = threadIdx.x;
    const int wid  = tid >> 5;
    const int lane = tid & 31;
    const int m0   = blockIdx.y * BM;
    const int n0   = blockIdx.x * BN;
    const int wm   = (wid >> 1) * 64;
    const int wn   = (wid & 1) * 64;
    const int M    = T_N;
    const int Kc   = 384;
    const uint32_t sbase = smem_u32(smem);

    int2* esm = (int2*)(smem + STG * STG_BYTES);
    {
        int gr = m0 + tid;
        esm[tid] = (gr < M) ? *(const int2*)&edges[2*gr] : make_int2(0, 0);
    }
    __syncthreads();

    AddrCtx cx; make_ctx(cx, wm, wn, lane);
    const int lrow = tid >> 3, lch = tid & 7;
    const uint32_t off0 = (uint32_t)(lrow * 128 + ((lch ^ (lrow & 7)) << 4));
    const __half* bBase = Bt + (size_t)(n0 + lrow) * Kc + lch * 8;

    float acc[4][8][4];
    #pragma unroll
    for (int i = 0; i < 4; i++)
        #pragma unroll
        for (int j = 0; j < 8; j++)
            #pragma unroll
            for (int k = 0; k < 4; k++) acc[i][j][k] = 0.f;

    auto ld_tile = [&](int it, int buf) {
        const int kp  = it * BK;
        const int reg = kp >> 7;          // 0: obj[s], 1: pred, 2: obj[o]
        const int kc  = (kp & 127) + lch * 8;
        uint32_t sa = sbase + buf * STG_BYTES;
        uint32_t sb = sa + 16384;
        #pragma unroll
        for (int t = 0; t < 8; t++) {
            int row = lrow + t * 16;
            const __half* src;
            if (reg == 0)      src = objh  + (size_t)esm[row].x * DIN + kc;
            else if (reg == 1) src = predh + (size_t)(m0 + row) * DIN + kc;
            else               src = objh  + (size_t)esm[row].y * DIN + kc;
            cp_async16(sa + off0 + t * 2048, src);
        }
        const __half* pb = bBase + kp;
        #pragma unroll
        for (int t = 0; t < 8; t++) {
            cp_async16(sb + off0 + t * 2048, pb);
            pb += 16 * Kc;
        }
    };

    const int NC = Kc / BK;   // 6
    ld_tile(0, 0);
    asm volatile("cp.async.commit_group;" ::: "memory");
    for (int it = 0; it < NC; it++) {
        asm volatile("cp.async.wait_group 0;" ::: "memory");
        __syncthreads();
        if (it + 1 < NC) ld_tile(it + 1, (it + 1) & 1);
        asm volatile("cp.async.commit_group;" ::: "memory");
        uint32_t sa = sbase + (it & 1) * STG_BYTES;
        compute_chunk(sa, sa + 16384, cx, acc);
    }

    float bc[8][2];
    #pragma unroll
    for (int nf = 0; nf < 8; nf++) {
        float2 bv = __ldg((const float2*)&bias[n0 + wn + nf * 8 + (lane & 3) * 2]);
        bc[nf][0] = bv.x; bc[nf][1] = bv.y;
    }
    #pragma unroll
    for (int mf = 0; mf < 4; mf++)
        #pragma unroll
        for (int rh = 0; rh < 2; rh++) {
            const int gr = m0 + wm + mf * 16 + (lane >> 2) + rh * 8;
            if (gr >= M) continue;
            #pragma unroll
            for (int nf = 0; nf < 8; nf++) {
                const int col = n0 + wn + nf * 8 + (lane & 3) * 2;
                float v0 = fmaxf(acc[mf][nf][rh*2+0] + bc[nf][0], 0.f);
                float v1 = fmaxf(acc[mf][nf][rh*2+1] + bc[nf][1], 0.f);
                __half2 hv = __halves2half2(__float2half_rn(v0), __float2half_rn(v1));
                // streaming store: h16 (205 MB) exceeds L2; don't evict bt1/objh
                st_cs_u32(&outh[(size_t)gr * HID + col], *(uint32_t*)&hv);
            }
        }
}

// ---------------- generic GEMM -------------------------------------------------
// A padded beyond M (garbage rows discarded by guarded epilogue).
// EPI 0: fp32 store (streaming)    EPI 2: GEMM2 router    EPI 3: fp16 store
template<int EPI>
__global__ void __launch_bounds__(128, 3)
mma_gemm(const __half* __restrict__ A, const __half* __restrict__ Bt,
         const float* __restrict__ bias, float* __restrict__ outf,
         __half* __restrict__ outh,
         int M, int strideA, int Kc, int ostride,
         const int* __restrict__ edges, float* __restrict__ pooled,
         float* __restrict__ newp)
{
    extern __shared__ char smem[];
    const int tid  = threadIdx.x;
    const int wid  = tid >> 5;
    const int lane = tid & 31;
    const int m0   = blockIdx.y * BM;
    const int n0   = blockIdx.x * BN;
    const int wm   = (wid >> 1) * 64;
    const int wn   = (wid & 1) * 64;
    const uint32_t sbase = smem_u32(smem);

    AddrCtx cx; make_ctx(cx, wm, wn, lane);
    const int lrow = tid >> 3, lch = tid & 7;
    const uint32_t off0 = (uint32_t)(lrow * 128 + ((lch ^ (lrow & 7)) << 4));
    const __half* aBase = A  + (size_t)(m0 + lrow) * strideA + lch * 8;
    const __half* bBase = Bt + (size_t)(n0 + lrow) * Kc      + lch * 8;

    float acc[4][8][4];
    #pragma unroll
    for (int i = 0; i < 4; i++)
        #pragma unroll
        for (int j = 0; j < 8; j++)
            #pragma unroll
            for (int k = 0; k < 4; k++) acc[i][j][k] = 0.f;

    auto ld_tile = [&](int it, int buf) {
        const int kp = it * BK;
        uint32_t sa = sbase + buf * STG_BYTES;
        uint32_t sb = sa + 16384;
        const __half* pa = aBase + kp;
        const __half* pb = bBase + kp;
        #pragma unroll
        for (int t = 0; t < 8; t++) {
            cp_async16(sa + off0 + t * 2048, pa);
            pa += 16 * strideA;
        }
        #pragma unroll
        for (int t = 0; t < 8; t++) {
            cp_async16(sb + off0 + t * 2048, pb);
            pb += 16 * Kc;
        }
    };

    const int NC = Kc / BK;
    ld_tile(0, 0);
    asm volatile("cp.async.commit_group;" ::: "memory");
    for (int it = 0; it < NC; it++) {
        asm volatile("cp.async.wait_group 0;" ::: "memory");
        __syncthreads();
        if (it + 1 < NC) ld_tile(it + 1, (it + 1) & 1);
        asm volatile("cp.async.commit_group;" ::: "memory");
        uint32_t sa = sbase + (it & 1) * STG_BYTES;
        compute_chunk(sa, sa + 16384, cx, acc);
    }

    float bc[8][2];
    #pragma unroll
    for (int nf = 0; nf < 8; nf++) {
        float2 bv = __ldg((const float2*)&bias[n0 + wn + nf * 8 + (lane & 3) * 2]);
        bc[nf][0] = bv.x; bc[nf][1] = bv.y;
    }

    #pragma unroll
    for (int mf = 0; mf < 4; mf++)
        #pragma unroll
        for (int rh = 0; rh < 2; rh++) {
            const int gr = m0 + wm + mf * 16 + (lane >> 2) + rh * 8;
            if (gr >= M) continue;
            int es = 0, eo = 0;
            if (EPI == 2) {
                int2 e = *(const int2*)&edges[2*gr];
                es = e.x; eo = e.y;
            }
            #pragma unroll
            for (int nf = 0; nf < 8; nf++) {
                const int col = n0 + wn + nf * 8 + (lane & 3) * 2;
                float v0 = fmaxf(acc[mf][nf][rh*2+0] + bc[nf][0], 0.f);
                float v1 = fmaxf(acc[mf][nf][rh*2+1] + bc[nf][1], 0.f);
                if (EPI == 0) {
                    // new_obj: final output, never re-read -> streaming
                    st_cs_f2(&outf[(size_t)gr * ostride + col], v0, v1);
                } else if (EPI == 3) {
                    // h2: re-read by GEMM4 immediately (51 MB) -> normal policy
                    *(__half2*)&outh[(size_t)gr * ostride + col] =
                        __halves2half2(__float2half_rn(v0), __float2half_rn(v1));
                } else {
                    if (col < HID) {
                        red_add2(&pooled[(size_t)es * HID + col], v0, v1);
                    } else if (col < HID + DOUT) {
                        // new_p: final output, never re-read -> streaming
                        st_cs_f2(&newp[(size_t)gr * DOUT + (col - HID)], v0, v1);
                    } else {
                        red_add2(&pooled[(size_t)eo * HID + (col - HID - DOUT)], v0, v1);
                    }
                }
            }
        }
}

// ---------------- launch ------------------------------------------------------
// 7 stream-ordered launches; GEMM2 remains launch #4 (the profiled slot).
//   1 memset(cnt)  2 prep_all  3 g1  4 GEMM2  5 pscale  6 GEMM3  7 GEMM4
extern "C" void kernel_launch(void* const* d_in, const int* in_sizes, int n_in,
                              void* d_out, int out_size) {
    const float* obj  = (const float*)d_in[0];
    const float* pred = (const float*)d_in[1];
    const int*   edges= (const int*)  d_in[2];
    const float* W1a  = (const float*)d_in[3];
    const float* b1a  = (const float*)d_in[4];
    const float* W1b  = (const float*)d_in[5];
    const float* b1b  = (const float*)d_in[6];
    const float* W2a  = (const float*)d_in[7];
    const float* b2a  = (const float*)d_in[8];
    const float* W2b  = (const float*)d_in[9];
    const float* b2b  = (const float*)d_in[10];

    float* out     = (float*)d_out;
    float* new_obj = out;                       // [O, 128]
    float* new_p   = out + (size_t)O_N * DOUT;  // [T, 128]

    __half *objh, *predh, *h16, *p16, *h2, *bt1, *bt2, *bt3, *bt4;
    float *pooled, *cnt;
    cudaGetSymbolAddress((void**)&objh,   g_objh);
    cudaGetSymbolAddress((void**)&predh,  g_predh);
    cudaGetSymbolAddress((void**)&h16,    g_h);
    cudaGetSymbolAddress((void**)&pooled, g_pool);
    cudaGetSymbolAddress((void**)&p16,    g_pool16);
    cudaGetSymbolAddress((void**)&h2,     g_h2);
    cudaGetSymbolAddress((void**)&cnt,    g_cnt);
    cudaGetSymbolAddress((void**)&bt1,    g_bt1);
    cudaGetSymbolAddress((void**)&bt2,    g_bt2);
    cudaGetSymbolAddress((void**)&bt3,    g_bt3);
    cudaGetSymbolAddress((void**)&bt4,    g_bt4);

    const int SMEM_G  = STG * STG_BYTES;          // 65536
    const int SMEM_G1 = SMEM_G + 128 * 8;         // + edge cache (1 KB)
    cudaFuncSetAttribute((const void*)g1_gemm,     cudaFuncAttributeMaxDynamicSharedMemorySize, SMEM_G1);
    cudaFuncSetAttribute((const void*)mma_gemm<0>, cudaFuncAttributeMaxDynamicSharedMemorySize, SMEM_G);
    cudaFuncSetAttribute((const void*)mma_gemm<2>, cudaFuncAttributeMaxDynamicSharedMemorySize, SMEM_G);
    cudaFuncSetAttribute((const void*)mma_gemm<3>, cudaFuncAttributeMaxDynamicSharedMemorySize, SMEM_G);

    const int MT_T = (T_N + 127) / 128;   // 1563
    const int MT_O = (O_N + 127) / 128;   // 391

    // 1: zero cnt (stream-ordered before prep_all's atomics)
    cudaMemsetAsync(cnt, 0, (size_t)O_N * sizeof(float));

    // 2: merged prep — zero pooled + obj/pred fp16 + weight transposes + counts
    {   int span = T_N * DIN / 4;   // 6.4M (covers all index spaces)
        prep_all<<<(span + 255) / 256, 256>>>(
            (const float4*)obj, (__half2*)objh,
            (const float4*)pred, (__half2*)predh,
            (float4*)pooled,
            W1a, W1b, W2a, W2b, bt1, bt2, bt3, bt4, edges, cnt); }

    // 3: GEMM1 (fused gather)
    g1_gemm<<<dim3(4, MT_T), 128, SMEM_G1>>>(objh, predh, edges, bt1, b1a, h16);

    // 4: GEMM2 (scatter s/o + new_p)   <-- profiled slot
    mma_gemm<2><<<dim3(9, MT_T), 128, SMEM_G>>>(
        h16, bt2, b1b, nullptr, nullptr,
        T_N, 512, 512, 0, edges, pooled, new_p);

    // 5: pooled scale + fp16
    pscale_conv<<<(O_N * (HID / 4) + 255) / 256, 256>>>((const float4*)pooled, cnt, p16);

    // 6: GEMM3
    mma_gemm<3><<<dim3(4, MT_O), 128, SMEM_G>>>(
        p16, bt3, b2a, nullptr, h2,
        O_N, 512, 512, HID, nullptr, nullptr, nullptr);

    // 7: GEMM4
    mma_gemm<0><<<dim3(1, MT_O), 128, SMEM_G>>>(
        h2, bt4, b2b, new_obj, nullptr,
        O_N, 512, 512, DOUT, nullptr, nullptr, nullptr);
}